// round 1
// baseline (speedup 1.0000x reference)
#include <cuda_runtime.h>
#include <math.h>

#define NLIG 1024
#define NPKT 8192
#define HID 256
#define ADIM 512
#define TABN 4096
#define CUTOFF 10.0f

// ---------------- device scratch (no allocations allowed) ----------------
__device__ float  g_K[NPKT * HID];
__device__ float  g_V[NPKT * HID];
__device__ float  g_Q[NLIG * HID];
__device__ float4 g_tab[TABN];

// ---------------- edge-bias lookup table -------------------------------
// f(d) = silu(d*e1w + e1b) @ e2w + e2b  is a scalar->4 function; tabulate on [0,10].
__global__ void build_table_kernel(const float* __restrict__ e1w,
                                   const float* __restrict__ e1b,
                                   const float* __restrict__ e2w,
                                   const float* __restrict__ e2b) {
    int e = blockIdx.x * blockDim.x + threadIdx.x;
    if (e >= TABN) return;
    float d = (float)e * (CUTOFF / (float)(TABN - 1));
    float a0 = e2b[0], a1 = e2b[1], a2 = e2b[2], a3 = e2b[3];
    for (int u = 0; u < HID; u++) {
        float z = fmaf(d, e1w[u], e1b[u]);
        float s = z / (1.0f + expf(-z));
        a0 = fmaf(s, e2w[u * 4 + 0], a0);
        a1 = fmaf(s, e2w[u * 4 + 1], a1);
        a2 = fmaf(s, e2w[u * 4 + 2], a2);
        a3 = fmaf(s, e2w[u * 4 + 3], a3);
    }
    g_tab[e] = make_float4(a0, a1, a2, a3);
}

// ---------------- fp32 tiled GEMM with bias: C = A@W + b ----------------
// BM=128, BN=64, BK=16, 256 threads, 8x4 register tile per thread.
__global__ __launch_bounds__(256) void gemm_bias(const float* __restrict__ A,
                                                 const float* __restrict__ W,
                                                 const float* __restrict__ bias,
                                                 float* __restrict__ C,
                                                 int M, int N, int Kd) {
    __shared__ float As[16][128];
    __shared__ float Bs[16][64];
    const int t = threadIdx.x;
    const int tx = t & 15, ty = t >> 4;
    const int bm = blockIdx.x * 128, bn = blockIdx.y * 64;

    float acc[8][4];
#pragma unroll
    for (int i = 0; i < 8; i++)
#pragma unroll
        for (int j = 0; j < 4; j++) acc[i][j] = 0.f;

    for (int kt = 0; kt < Kd; kt += 16) {
        // load A tile (128x16) transposed into As[k][m]
#pragma unroll
        for (int i = 0; i < 2; i++) {
            int s = t * 2 + i;           // 512 float4 slots
            int row = s >> 2, c4 = s & 3;
            float4 v = *(const float4*)(A + (size_t)(bm + row) * Kd + kt + c4 * 4);
            As[c4 * 4 + 0][row] = v.x;
            As[c4 * 4 + 1][row] = v.y;
            As[c4 * 4 + 2][row] = v.z;
            As[c4 * 4 + 3][row] = v.w;
        }
        // load B tile (16x64)
        {
            int row = t >> 4, c4 = t & 15;
            float4 v = *(const float4*)(W + (size_t)(kt + row) * N + bn + c4 * 4);
            *(float4*)&Bs[row][c4 * 4] = v;
        }
        __syncthreads();
#pragma unroll
        for (int k = 0; k < 16; k++) {
            float a[8], b[4];
#pragma unroll
            for (int i = 0; i < 8; i++) a[i] = As[k][ty * 8 + i];
#pragma unroll
            for (int j = 0; j < 4; j++) b[j] = Bs[k][tx * 4 + j];
#pragma unroll
            for (int i = 0; i < 8; i++)
#pragma unroll
                for (int j = 0; j < 4; j++) acc[i][j] = fmaf(a[i], b[j], acc[i][j]);
        }
        __syncthreads();
    }
#pragma unroll
    for (int i = 0; i < 8; i++) {
        int row = bm + ty * 8 + i;
#pragma unroll
        for (int j = 0; j < 4; j++) {
            int col = bn + tx * 4 + j;
            C[(size_t)row * N + col] = acc[i][j] + bias[col];
        }
    }
}

// ---------------- main attention kernel: one block per ligand ----------
__global__ __launch_bounds__(256) void attn_kernel(
    const float* __restrict__ h_lig, const float* __restrict__ x_lig,
    const float* __restrict__ x_pocket,
    const float* __restrict__ ow, const float* __restrict__ ob,
    const float* __restrict__ c1w, const float* __restrict__ c1b,
    const float* __restrict__ c2w, const float* __restrict__ c2b,
    float* __restrict__ out) {
    const int i = blockIdx.x;
    const int t = threadIdx.x;
    const int w = t >> 5, lane = t & 31;

    __shared__ float q_s[HID];
    __shared__ unsigned short list[NPKT];
    __shared__ float wm[8][4], wl[8][4], wc[8][12];
    __shared__ float wv[8][HID];
    __shared__ float h_s[HID];
    __shared__ float tmp12[12];
    __shared__ float cm_s[3];
    __shared__ int woff[8];
    __shared__ int s_cnt;
    __shared__ float s_xl[3];

    if (t < 3) s_xl[t] = x_lig[i * 3 + t];
    q_s[t] = g_Q[(size_t)i * HID + t];
    __syncthreads();
    const float xlx = s_xl[0], xly = s_xl[1], xlz = s_xl[2];

    // ---- Phase A: deterministic compaction of active pocket atoms ----
    int mycnt = 0;
    const int jbase = t * 32;  // 8192 = 256 * 32, blocked assignment -> deterministic order
#pragma unroll 4
    for (int k = 0; k < 32; k++) {
        int j = jbase + k;
        float rx = x_pocket[j * 3 + 0] - xlx;
        float ry = x_pocket[j * 3 + 1] - xly;
        float rz = x_pocket[j * 3 + 2] - xlz;
        float d = sqrtf(rx * rx + ry * ry + rz * rz);
        mycnt += (d < CUTOFF) ? 1 : 0;
    }
    int inc = mycnt;
#pragma unroll
    for (int off = 1; off < 32; off <<= 1) {
        int v = __shfl_up_sync(0xffffffffu, inc, off);
        if (lane >= off) inc += v;
    }
    if (lane == 31) woff[w] = inc;  // warp totals
    __syncthreads();
    if (t == 0) {
        int run = 0;
#pragma unroll
        for (int ww = 0; ww < 8; ww++) { int v = woff[ww]; woff[ww] = run; run += v; }
        s_cnt = run;
    }
    __syncthreads();
    int offset = woff[w] + (inc - mycnt);
#pragma unroll 4
    for (int k = 0; k < 32; k++) {
        int j = jbase + k;
        float rx = x_pocket[j * 3 + 0] - xlx;
        float ry = x_pocket[j * 3 + 1] - xly;
        float rz = x_pocket[j * 3 + 2] - xlz;
        float d = sqrtf(rx * rx + ry * ry + rz * rz);
        if (d < CUTOFF) list[offset++] = (unsigned short)j;
    }
    __syncthreads();
    const int nact = s_cnt;

    // ---- Phase B: per-warp online softmax over active list ----
    float q[8];
#pragma unroll
    for (int k = 0; k < 8; k++) q[k] = q_s[lane * 8 + k];
    const int h = lane >> 3;  // lane's feature chunk [lane*8, lane*8+8) lies in head lane/8

    float m0 = -INFINITY, m1 = -INFINITY, m2 = -INFINITY, m3 = -INFINITY;
    float l0 = 0.f, l1 = 0.f, l2 = 0.f, l3 = 0.f;
    float c00 = 0.f, c01 = 0.f, c02 = 0.f;
    float c10 = 0.f, c11 = 0.f, c12 = 0.f;
    float c20 = 0.f, c21 = 0.f, c22 = 0.f;
    float c30 = 0.f, c31 = 0.f, c32 = 0.f;
    float av[8];
#pragma unroll
    for (int k = 0; k < 8; k++) av[k] = 0.f;

    for (int p = w; p < nact; p += 8) {
        const int jj = list[p];
        float px = x_pocket[jj * 3 + 0];
        float py = x_pocket[jj * 3 + 1];
        float pz = x_pocket[jj * 3 + 2];
        float rx = px - xlx, ry = py - xly, rz = pz - xlz;
        float d = sqrtf(rx * rx + ry * ry + rz * rz);
        float invd = __fdividef(1.0f, d + 1e-8f);
        float nrx = rx * invd, nry = ry * invd, nrz = rz * invd;

        // edge bias via table lerp
        float tp = d * ((float)(TABN - 1) / CUTOFF);
        int k0 = (int)tp;
        k0 = (k0 > TABN - 2) ? (TABN - 2) : k0;
        float fr = tp - (float)k0;
        float4 f0 = g_tab[k0], f1 = g_tab[k0 + 1];
        float e0 = f0.x + fr * (f1.x - f0.x);
        float e1 = f0.y + fr * (f1.y - f0.y);
        float e2v = f0.z + fr * (f1.z - f0.z);
        float e3 = f0.w + fr * (f1.w - f0.w);

        // Q.K per head: lane loads 8 contiguous K features (coalesced 128B x8)
        const float4* Kp = (const float4*)(g_K + (size_t)jj * HID + lane * 8);
        float4 ka = Kp[0], kb4 = Kp[1];
        float dp = q[0] * ka.x + q[1] * ka.y + q[2] * ka.z + q[3] * ka.w +
                   q[4] * kb4.x + q[5] * kb4.y + q[6] * kb4.z + q[7] * kb4.w;
        dp += __shfl_xor_sync(0xffffffffu, dp, 1);
        dp += __shfl_xor_sync(0xffffffffu, dp, 2);
        dp += __shfl_xor_sync(0xffffffffu, dp, 4);
        float s0 = fmaf(__shfl_sync(0xffffffffu, dp, 0), 0.125f, e0);
        float s1 = fmaf(__shfl_sync(0xffffffffu, dp, 8), 0.125f, e1);
        float s2 = fmaf(__shfl_sync(0xffffffffu, dp, 16), 0.125f, e2v);
        float s3 = fmaf(__shfl_sync(0xffffffffu, dp, 24), 0.125f, e3);

        // online softmax update (warp-uniform values)
        float nm0 = fmaxf(m0, s0), nm1 = fmaxf(m1, s1);
        float nm2 = fmaxf(m2, s2), nm3 = fmaxf(m3, s3);
        float sc0 = __expf(m0 - nm0), p0 = __expf(s0 - nm0);
        float sc1 = __expf(m1 - nm1), p1 = __expf(s1 - nm1);
        float sc2 = __expf(m2 - nm2), p2 = __expf(s2 - nm2);
        float sc3 = __expf(m3 - nm3), p3 = __expf(s3 - nm3);
        m0 = nm0; m1 = nm1; m2 = nm2; m3 = nm3;
        l0 = l0 * sc0 + p0; l1 = l1 * sc1 + p1;
        l2 = l2 * sc2 + p2; l3 = l3 * sc3 + p3;
        c00 = c00 * sc0 + p0 * nrx; c01 = c01 * sc0 + p0 * nry; c02 = c02 * sc0 + p0 * nrz;
        c10 = c10 * sc1 + p1 * nrx; c11 = c11 * sc1 + p1 * nry; c12 = c12 * sc1 + p1 * nrz;
        c20 = c20 * sc2 + p2 * nrx; c21 = c21 * sc2 + p2 * nry; c22 = c22 * sc2 + p2 * nrz;
        c30 = c30 * sc3 + p3 * nrx; c31 = c31 * sc3 + p3 * nry; c32 = c32 * sc3 + p3 * nrz;

        float ph  = (h == 0) ? p0  : ((h == 1) ? p1  : ((h == 2) ? p2  : p3));
        float sch = (h == 0) ? sc0 : ((h == 1) ? sc1 : ((h == 2) ? sc2 : sc3));
        const float4* Vp = (const float4*)(g_V + (size_t)jj * HID + lane * 8);
        float4 va = Vp[0], vb4 = Vp[1];
        av[0] = av[0] * sch + ph * va.x;  av[1] = av[1] * sch + ph * va.y;
        av[2] = av[2] * sch + ph * va.z;  av[3] = av[3] * sch + ph * va.w;
        av[4] = av[4] * sch + ph * vb4.x; av[5] = av[5] * sch + ph * vb4.y;
        av[6] = av[6] * sch + ph * vb4.z; av[7] = av[7] * sch + ph * vb4.w;
    }

    // ---- write warp partials ----
#pragma unroll
    for (int k = 0; k < 8; k++) wv[w][lane * 8 + k] = av[k];
    if (lane == 0) {
        wm[w][0] = m0; wm[w][1] = m1; wm[w][2] = m2; wm[w][3] = m3;
        wl[w][0] = l0; wl[w][1] = l1; wl[w][2] = l2; wl[w][3] = l3;
        wc[w][0] = c00; wc[w][1] = c01; wc[w][2]  = c02;
        wc[w][3] = c10; wc[w][4] = c11; wc[w][5]  = c12;
        wc[w][6] = c20; wc[w][7] = c21; wc[w][8]  = c22;
        wc[w][9] = c30; wc[w][10] = c31; wc[w][11] = c32;
    }
    __syncthreads();

    // ---- merge across warps ----
    {
        int hh = t >> 6;
        float M = -INFINITY;
#pragma unroll
        for (int w2 = 0; w2 < 8; w2++) M = fmaxf(M, wm[w2][hh]);
        float L = 0.f, hv = 0.f;
        if (M > -1e37f) {
#pragma unroll
            for (int w2 = 0; w2 < 8; w2++) {
                float e = __expf(wm[w2][hh] - M);
                L = fmaf(wl[w2][hh], e, L);
                hv = fmaf(wv[w2][t], e, hv);
            }
        }
        h_s[t] = (L > 0.f) ? hv / L : 0.f;

        if (t < 12) {
            int h2 = t / 3, ax = t % 3;
            float M2 = -INFINITY;
#pragma unroll
            for (int w2 = 0; w2 < 8; w2++) M2 = fmaxf(M2, wm[w2][h2]);
            float L2 = 0.f, cv = 0.f;
            if (M2 > -1e37f) {
#pragma unroll
                for (int w2 = 0; w2 < 8; w2++) {
                    float e = __expf(wm[w2][h2] - M2);
                    L2 = fmaf(wl[w2][h2], e, L2);
                    cv = fmaf(wc[w2][h2 * 3 + ax], e, cv);
                }
            }
            tmp12[t] = (L2 > 0.f) ? cv / L2 : 0.f;
        }
    }
    __syncthreads();
    if (t < 3) cm_s[t] = 0.25f * (tmp12[t] + tmp12[t + 3] + tmp12[t + 6] + tmp12[t + 9]);
    __syncthreads();

    // ---- fused epilogue: h_out = h_lig + h_att@ow + ob ;  coord scale ----
    float acc = ob[t];
    float g = c1b[t];
#pragma unroll 8
    for (int k = 0; k < HID; k++) {
        float hk = h_s[k];
        acc = fmaf(hk, ow[(size_t)k * HID + t], acc);
        g = fmaf(hk, c1w[(size_t)k * HID + t], g);
    }
    out[(size_t)i * HID + t] = h_lig[(size_t)i * HID + t] + acc;
    g = g / (1.0f + __expf(-g));  // silu
    float contrib = g * c2w[t];
#pragma unroll
    for (int off = 16; off; off >>= 1) contrib += __shfl_xor_sync(0xffffffffu, contrib, off);
    if (lane == 0) tmp12[w] = contrib;  // reuse (cm_s already extracted)
    __syncthreads();
    if (t == 0) {
        float sres = c2b[0];
#pragma unroll
        for (int ww = 0; ww < 8; ww++) sres += tmp12[ww];
        float* outx = out + (size_t)NLIG * HID;
#pragma unroll
        for (int ax = 0; ax < 3; ax++)
            outx[i * 3 + ax] = x_lig[i * 3 + ax] + sres * cm_s[ax];
    }
}

// ---------------- launch ----------------
extern "C" void kernel_launch(void* const* d_in, const int* in_sizes, int n_in,
                              void* d_out, int out_size) {
    const float* h_lig = (const float*)d_in[0];
    const float* x_lig = (const float*)d_in[1];
    const float* h_atm = (const float*)d_in[2];
    const float* x_pkt = (const float*)d_in[3];
    const float* qw = (const float*)d_in[4];
    const float* qb = (const float*)d_in[5];
    const float* kw = (const float*)d_in[6];
    const float* kb = (const float*)d_in[7];
    const float* vw = (const float*)d_in[8];
    const float* vb = (const float*)d_in[9];
    const float* ow = (const float*)d_in[10];
    const float* ob = (const float*)d_in[11];
    const float* e1w = (const float*)d_in[12];
    const float* e1b = (const float*)d_in[13];
    const float* e2w = (const float*)d_in[14];
    const float* e2b = (const float*)d_in[15];
    const float* c1w = (const float*)d_in[16];
    const float* c1b = (const float*)d_in[17];
    const float* c2w = (const float*)d_in[18];
    const float* c2b = (const float*)d_in[19];
    float* out = (float*)d_out;

    float *Kp, *Vp, *Qp;
    cudaGetSymbolAddress((void**)&Kp, g_K);
    cudaGetSymbolAddress((void**)&Vp, g_V);
    cudaGetSymbolAddress((void**)&Qp, g_Q);

    build_table_kernel<<<(TABN + 255) / 256, 256>>>(e1w, e1b, e2w, e2b);
    gemm_bias<<<dim3(NLIG / 128, HID / 64), 256>>>(h_lig, qw, qb, Qp, NLIG, HID, HID);
    gemm_bias<<<dim3(NPKT / 128, HID / 64), 256>>>(h_atm, kw, kb, Kp, NPKT, HID, ADIM);
    gemm_bias<<<dim3(NPKT / 128, HID / 64), 256>>>(h_atm, vw, vb, Vp, NPKT, HID, ADIM);
    attn_kernel<<<NLIG, 256>>>(h_lig, x_lig, x_pkt, ow, ob, c1w, c1b, c2w, c2b, out);
}

// round 2
// speedup vs baseline: 1.7187x; 1.7187x over previous
#include <cuda_runtime.h>
#include <cuda_bf16.h>
#include <math.h>

#define NLIG 1024
#define NPKT 8192
#define HID 256
#define ADIM 512
#define TABN 4096
#define CUTOFF 10.0f
#define CAP 2048

// ---------------- device scratch ----------------
__device__ float          g_K[NPKT * HID];
__device__ __nv_bfloat16  g_Vbf[NPKT * HID];
__device__ float          g_Q[NLIG * HID];
__device__ float          g_hatt[NLIG * HID];
__device__ float          g_t2[NLIG * HID];
__device__ float4         g_cm[NLIG];
__device__ float4         g_xp4[NPKT];
__device__ float4         g_tab[TABN];

// ---------------- helpers ----------------
__device__ __forceinline__ float wsum(float v) {
    v += __shfl_xor_sync(0xffffffffu, v, 16);
    v += __shfl_xor_sync(0xffffffffu, v, 8);
    v += __shfl_xor_sync(0xffffffffu, v, 4);
    v += __shfl_xor_sync(0xffffffffu, v, 2);
    v += __shfl_xor_sync(0xffffffffu, v, 1);
    return v;
}
__device__ __forceinline__ float wmax(float v) {
    v = fmaxf(v, __shfl_xor_sync(0xffffffffu, v, 16));
    v = fmaxf(v, __shfl_xor_sync(0xffffffffu, v, 8));
    v = fmaxf(v, __shfl_xor_sync(0xffffffffu, v, 4));
    v = fmaxf(v, __shfl_xor_sync(0xffffffffu, v, 2));
    v = fmaxf(v, __shfl_xor_sync(0xffffffffu, v, 1));
    return v;
}

// ---------------- x_pocket -> padded float4 ----------------
__global__ void prep_xp4(const float* __restrict__ xp) {
    int j = blockIdx.x * 256 + threadIdx.x;
    if (j < NPKT)
        g_xp4[j] = make_float4(xp[j * 3 + 0], xp[j * 3 + 1], xp[j * 3 + 2], 0.f);
}

// ---------------- edge-bias lookup table ----------------
__global__ void build_table_kernel(const float* __restrict__ e1w,
                                   const float* __restrict__ e1b,
                                   const float* __restrict__ e2w,
                                   const float* __restrict__ e2b) {
    int e = blockIdx.x * blockDim.x + threadIdx.x;
    if (e >= TABN) return;
    float d = (float)e * (CUTOFF / (float)(TABN - 1));
    float a0 = e2b[0], a1 = e2b[1], a2 = e2b[2], a3 = e2b[3];
    for (int u = 0; u < HID; u++) {
        float z = fmaf(d, e1w[u], e1b[u]);
        float s = z / (1.0f + expf(-z));
        a0 = fmaf(s, e2w[u * 4 + 0], a0);
        a1 = fmaf(s, e2w[u * 4 + 1], a1);
        a2 = fmaf(s, e2w[u * 4 + 2], a2);
        a3 = fmaf(s, e2w[u * 4 + 3], a3);
    }
    g_tab[e] = make_float4(a0, a1, a2, a3);
}

// ---------------- 64x64x16 fp32 GEMM, bias + optional residual ----------------
template <bool BF16OUT>
__global__ __launch_bounds__(256) void gemm64(const float* __restrict__ A,
                                              const float* __restrict__ W,
                                              const float* __restrict__ bias,
                                              const float* __restrict__ R,
                                              void* __restrict__ Cv,
                                              int M, int N, int Kd) {
    __shared__ float As[64][16];
    __shared__ float Bs[16][64];
    const int t = threadIdx.x;
    const int tx = t & 15, ty = t >> 4;
    const int bm = blockIdx.x * 64, bn = blockIdx.y * 64;
    const int arow = t >> 2, ac4 = (t & 3) * 4;
    const int brow = t >> 4, bc4 = (t & 15) * 4;

    float acc[4][4];
#pragma unroll
    for (int i = 0; i < 4; i++)
#pragma unroll
        for (int j = 0; j < 4; j++) acc[i][j] = 0.f;

    for (int kt = 0; kt < Kd; kt += 16) {
        float4 av = *(const float4*)(A + (size_t)(bm + arow) * Kd + kt + ac4);
        float4 bv = *(const float4*)(W + (size_t)(kt + brow) * N + bn + bc4);
        *(float4*)&As[arow][ac4] = av;
        *(float4*)&Bs[brow][bc4] = bv;
        __syncthreads();
#pragma unroll
        for (int k = 0; k < 16; k++) {
            float4 bq = *(const float4*)&Bs[k][tx * 4];
            float a0 = As[ty * 4 + 0][k];
            float a1 = As[ty * 4 + 1][k];
            float a2 = As[ty * 4 + 2][k];
            float a3 = As[ty * 4 + 3][k];
            acc[0][0] = fmaf(a0, bq.x, acc[0][0]); acc[0][1] = fmaf(a0, bq.y, acc[0][1]);
            acc[0][2] = fmaf(a0, bq.z, acc[0][2]); acc[0][3] = fmaf(a0, bq.w, acc[0][3]);
            acc[1][0] = fmaf(a1, bq.x, acc[1][0]); acc[1][1] = fmaf(a1, bq.y, acc[1][1]);
            acc[1][2] = fmaf(a1, bq.z, acc[1][2]); acc[1][3] = fmaf(a1, bq.w, acc[1][3]);
            acc[2][0] = fmaf(a2, bq.x, acc[2][0]); acc[2][1] = fmaf(a2, bq.y, acc[2][1]);
            acc[2][2] = fmaf(a2, bq.z, acc[2][2]); acc[2][3] = fmaf(a2, bq.w, acc[2][3]);
            acc[3][0] = fmaf(a3, bq.x, acc[3][0]); acc[3][1] = fmaf(a3, bq.y, acc[3][1]);
            acc[3][2] = fmaf(a3, bq.z, acc[3][2]); acc[3][3] = fmaf(a3, bq.w, acc[3][3]);
        }
        __syncthreads();
    }

#pragma unroll
    for (int i = 0; i < 4; i++) {
        int row = bm + ty * 4 + i;
        int col = bn + tx * 4;
        float v0 = acc[i][0] + bias[col + 0];
        float v1 = acc[i][1] + bias[col + 1];
        float v2 = acc[i][2] + bias[col + 2];
        float v3 = acc[i][3] + bias[col + 3];
        if (R) {
            float4 r = *(const float4*)(R + (size_t)row * N + col);
            v0 += r.x; v1 += r.y; v2 += r.z; v3 += r.w;
        }
        if (BF16OUT) {
            __nv_bfloat16* C = (__nv_bfloat16*)Cv;
            __nv_bfloat162 p0 = __floats2bfloat162_rn(v0, v1);
            __nv_bfloat162 p1 = __floats2bfloat162_rn(v2, v3);
            *(__nv_bfloat162*)(C + (size_t)row * N + col) = p0;
            *(__nv_bfloat162*)(C + (size_t)row * N + col + 2) = p1;
        } else {
            float* C = (float*)Cv;
            *(float4*)(C + (size_t)row * N + col) = make_float4(v0, v1, v2, v3);
        }
    }
}

// ---------------- attention kernel: one block per ligand ----------------
__global__ __launch_bounds__(256) void attn_kernel(const float* __restrict__ x_lig) {
    const int i = blockIdx.x;
    const int t = threadIdx.x;
    const int w = t >> 5, lane = t & 31;
    const int h = lane >> 3;

    __shared__ float q_s[HID];                 // 1 KB
    __shared__ unsigned short list[CAP];       // 4 KB
    __shared__ float4 sarr[CAP];               // 32 KB (scores -> probs)
    __shared__ float wv[8][HID];               // 8 KB
    __shared__ float wred[8][4];               // max / l partials
    __shared__ float wc[8][12];
    __shared__ float m_s[4], linv_s[4];
    __shared__ float c12[12];
    __shared__ int woff[8];
    __shared__ int s_cnt;
    __shared__ float s_xl[3];

    if (t < 3) s_xl[t] = x_lig[i * 3 + t];
    q_s[t] = g_Q[(size_t)i * HID + t];
    __syncthreads();
    const float xlx = s_xl[0], xly = s_xl[1], xlz = s_xl[2];

    // ---- Phase A: deterministic compaction (bitmask, blocked by thread) ----
    unsigned msk = 0;
    const int jbase = t * 32;
#pragma unroll 4
    for (int k = 0; k < 32; k++) {
        float4 xp = g_xp4[jbase + k];
        float rx = xp.x - xlx, ry = xp.y - xly, rz = xp.z - xlz;
        float d = sqrtf(rx * rx + ry * ry + rz * rz);
        if (d < CUTOFF) msk |= (1u << k);
    }
    int mycnt = __popc(msk);
    int inc = mycnt;
#pragma unroll
    for (int off = 1; off < 32; off <<= 1) {
        int v = __shfl_up_sync(0xffffffffu, inc, off);
        if (lane >= off) inc += v;
    }
    if (lane == 31) woff[w] = inc;
    __syncthreads();
    if (t == 0) {
        int run = 0;
#pragma unroll
        for (int ww = 0; ww < 8; ww++) { int v = woff[ww]; woff[ww] = run; run += v; }
        s_cnt = run;
    }
    __syncthreads();
    int offset = woff[w] + (inc - mycnt);
    unsigned mm = msk;
    while (mm) {
        int k = __ffs(mm) - 1;
        mm &= mm - 1;
        if (offset < CAP) list[offset] = (unsigned short)(jbase + k);
        offset++;
    }
    __syncthreads();
    const int nact = (s_cnt < CAP) ? s_cnt : CAP;

    // ---- B1: warp-per-pair raw Q.K dots ----
    {
        const float4* qv = (const float4*)q_s + lane * 2;
        const float4 qa = qv[0], qb = qv[1];
        for (int p = w; p < nact; p += 8) {
            const int jj = list[p];
            const float4* Kp = (const float4*)(g_K + (size_t)jj * HID) + lane * 2;
            float4 ka = Kp[0], kb = Kp[1];
            float dp = qa.x * ka.x + qa.y * ka.y + qa.z * ka.z + qa.w * ka.w +
                       qb.x * kb.x + qb.y * kb.y + qb.z * kb.z + qb.w * kb.w;
            dp += __shfl_xor_sync(0xffffffffu, dp, 1);
            dp += __shfl_xor_sync(0xffffffffu, dp, 2);
            dp += __shfl_xor_sync(0xffffffffu, dp, 4);
            float s0 = __shfl_sync(0xffffffffu, dp, 0);
            float s1 = __shfl_sync(0xffffffffu, dp, 8);
            float s2 = __shfl_sync(0xffffffffu, dp, 16);
            float s3 = __shfl_sync(0xffffffffu, dp, 24);
            if (lane == 0) sarr[p] = make_float4(s0, s1, s2, s3);
        }
    }
    __syncthreads();

    // ---- B2a pass 1: thread-per-pair: scale + edge bias, running max ----
    float mx0 = -INFINITY, mx1 = -INFINITY, mx2 = -INFINITY, mx3 = -INFINITY;
    for (int p = t; p < nact; p += 256) {
        float4 s = sarr[p];
        const int jj = list[p];
        float4 xp = g_xp4[jj];
        float rx = xp.x - xlx, ry = xp.y - xly, rz = xp.z - xlz;
        float d = sqrtf(rx * rx + ry * ry + rz * rz);
        float tp = d * ((float)(TABN - 1) / CUTOFF);
        int k0 = (int)tp;
        k0 = (k0 > TABN - 2) ? (TABN - 2) : k0;
        float fr = tp - (float)k0;
        float4 f0 = g_tab[k0], f1 = g_tab[k0 + 1];
        s.x = fmaf(s.x, 0.125f, f0.x + fr * (f1.x - f0.x));
        s.y = fmaf(s.y, 0.125f, f0.y + fr * (f1.y - f0.y));
        s.z = fmaf(s.z, 0.125f, f0.z + fr * (f1.z - f0.z));
        s.w = fmaf(s.w, 0.125f, f0.w + fr * (f1.w - f0.w));
        sarr[p] = s;
        mx0 = fmaxf(mx0, s.x); mx1 = fmaxf(mx1, s.y);
        mx2 = fmaxf(mx2, s.z); mx3 = fmaxf(mx3, s.w);
    }
    mx0 = wmax(mx0); mx1 = wmax(mx1); mx2 = wmax(mx2); mx3 = wmax(mx3);
    if (lane == 0) { wred[w][0] = mx0; wred[w][1] = mx1; wred[w][2] = mx2; wred[w][3] = mx3; }
    __syncthreads();
    if (t < 4) {
        float m = -INFINITY;
#pragma unroll
        for (int w2 = 0; w2 < 8; w2++) m = fmaxf(m, wred[w2][t]);
        m_s[t] = m;
    }
    __syncthreads();
    const float m0 = m_s[0], m1 = m_s[1], m2 = m_s[2], m3 = m_s[3];

    // ---- B2a pass 2: exp, l-sums, coord sums ----
    float l0 = 0.f, l1 = 0.f, l2 = 0.f, l3 = 0.f;
    float c[12];
#pragma unroll
    for (int j = 0; j < 12; j++) c[j] = 0.f;
    for (int p = t; p < nact; p += 256) {
        float4 s = sarr[p];
        float p0 = __expf(s.x - m0);
        float p1 = __expf(s.y - m1);
        float p2 = __expf(s.z - m2);
        float p3 = __expf(s.w - m3);
        sarr[p] = make_float4(p0, p1, p2, p3);
        l0 += p0; l1 += p1; l2 += p2; l3 += p3;
        const int jj = list[p];
        float4 xp = g_xp4[jj];
        float rx = xp.x - xlx, ry = xp.y - xly, rz = xp.z - xlz;
        float d = sqrtf(rx * rx + ry * ry + rz * rz);
        float invd = __fdividef(1.0f, d + 1e-8f);
        float nrx = rx * invd, nry = ry * invd, nrz = rz * invd;
        c[0] = fmaf(p0, nrx, c[0]); c[1]  = fmaf(p0, nry, c[1]);  c[2]  = fmaf(p0, nrz, c[2]);
        c[3] = fmaf(p1, nrx, c[3]); c[4]  = fmaf(p1, nry, c[4]);  c[5]  = fmaf(p1, nrz, c[5]);
        c[6] = fmaf(p2, nrx, c[6]); c[7]  = fmaf(p2, nry, c[7]);  c[8]  = fmaf(p2, nrz, c[8]);
        c[9] = fmaf(p3, nrx, c[9]); c[10] = fmaf(p3, nry, c[10]); c[11] = fmaf(p3, nrz, c[11]);
    }
    l0 = wsum(l0); l1 = wsum(l1); l2 = wsum(l2); l3 = wsum(l3);
#pragma unroll
    for (int j = 0; j < 12; j++) c[j] = wsum(c[j]);
    if (lane == 0) {
        wred[w][0] = l0; wred[w][1] = l1; wred[w][2] = l2; wred[w][3] = l3;
#pragma unroll
        for (int j = 0; j < 12; j++) wc[w][j] = c[j];
    }
    __syncthreads();
    if (t < 4) {
        float L = 0.f;
#pragma unroll
        for (int w2 = 0; w2 < 8; w2++) L += wred[w2][t];
        linv_s[t] = (L > 0.f) ? __fdividef(1.0f, L) : 0.f;
    }
    if (t >= 32 && t < 44) {
        int j = t - 32;
        float cc = 0.f;
#pragma unroll
        for (int w2 = 0; w2 < 8; w2++) cc += wc[w2][j];
        c12[j] = cc;
    }
    __syncthreads();
    if (t < 3) {
        float v = 0.f;
#pragma unroll
        for (int h2 = 0; h2 < 4; h2++) v += c12[h2 * 3 + t] * linv_s[h2];
        ((float*)&g_cm[i])[t] = 0.25f * v;
    }

    // ---- B2b: warp-per-pair weighted V accumulation (bf16 V) ----
    float av[8];
#pragma unroll
    for (int k = 0; k < 8; k++) av[k] = 0.f;
    const float* pef = (const float*)sarr;
    for (int p = w; p < nact; p += 8) {
        const int jj = list[p];
        float pe = pef[p * 4 + h];
        const __nv_bfloat162* Vp =
            (const __nv_bfloat162*)(g_Vbf + (size_t)jj * HID + lane * 8);
        float2 v0 = __bfloat1622float2(Vp[0]);
        float2 v1 = __bfloat1622float2(Vp[1]);
        float2 v2 = __bfloat1622float2(Vp[2]);
        float2 v3 = __bfloat1622float2(Vp[3]);
        av[0] = fmaf(pe, v0.x, av[0]); av[1] = fmaf(pe, v0.y, av[1]);
        av[2] = fmaf(pe, v1.x, av[2]); av[3] = fmaf(pe, v1.y, av[3]);
        av[4] = fmaf(pe, v2.x, av[4]); av[5] = fmaf(pe, v2.y, av[5]);
        av[6] = fmaf(pe, v3.x, av[6]); av[7] = fmaf(pe, v3.y, av[7]);
    }
#pragma unroll
    for (int k = 0; k < 8; k++) wv[w][lane * 8 + k] = av[k];
    __syncthreads();
    {
        float hv = 0.f;
#pragma unroll
        for (int w2 = 0; w2 < 8; w2++) hv += wv[w2][t];
        g_hatt[(size_t)i * HID + t] = hv * linv_s[t >> 6];
    }
}

// ---------------- finalize: coord scale + x_out ----------------
__global__ __launch_bounds__(256) void finalize_kernel(const float* __restrict__ x_lig,
                                                       const float* __restrict__ c2w,
                                                       const float* __restrict__ c2b,
                                                       float* __restrict__ out) {
    const int lig = blockIdx.x * 8 + (threadIdx.x >> 5);
    const int lane = threadIdx.x & 31;
    const float4* t2 = (const float4*)(g_t2 + (size_t)lig * HID) + lane * 2;
    float4 a = t2[0], b = t2[1];
    const float4* cw = (const float4*)c2w + lane * 2;
    float4 ca = cw[0], cb = cw[1];
    float s = 0.f;
    s = fmaf(a.x / (1.f + __expf(-a.x)), ca.x, s);
    s = fmaf(a.y / (1.f + __expf(-a.y)), ca.y, s);
    s = fmaf(a.z / (1.f + __expf(-a.z)), ca.z, s);
    s = fmaf(a.w / (1.f + __expf(-a.w)), ca.w, s);
    s = fmaf(b.x / (1.f + __expf(-b.x)), cb.x, s);
    s = fmaf(b.y / (1.f + __expf(-b.y)), cb.y, s);
    s = fmaf(b.z / (1.f + __expf(-b.z)), cb.z, s);
    s = fmaf(b.w / (1.f + __expf(-b.w)), cb.w, s);
    s = wsum(s);
    if (lane == 0) {
        s += c2b[0];
        float4 cm = g_cm[lig];
        float* ox = out + (size_t)NLIG * HID + lig * 3;
        ox[0] = x_lig[lig * 3 + 0] + s * cm.x;
        ox[1] = x_lig[lig * 3 + 1] + s * cm.y;
        ox[2] = x_lig[lig * 3 + 2] + s * cm.z;
    }
}

// ---------------- launch ----------------
extern "C" void kernel_launch(void* const* d_in, const int* in_sizes, int n_in,
                              void* d_out, int out_size) {
    const float* h_lig = (const float*)d_in[0];
    const float* x_lig = (const float*)d_in[1];
    const float* h_atm = (const float*)d_in[2];
    const float* x_pkt = (const float*)d_in[3];
    const float* qw = (const float*)d_in[4];
    const float* qb = (const float*)d_in[5];
    const float* kw = (const float*)d_in[6];
    const float* kb = (const float*)d_in[7];
    const float* vw = (const float*)d_in[8];
    const float* vb = (const float*)d_in[9];
    const float* ow = (const float*)d_in[10];
    const float* ob = (const float*)d_in[11];
    const float* e1w = (const float*)d_in[12];
    const float* e1b = (const float*)d_in[13];
    const float* e2w = (const float*)d_in[14];
    const float* e2b = (const float*)d_in[15];
    const float* c1w = (const float*)d_in[16];
    const float* c1b = (const float*)d_in[17];
    const float* c2w = (const float*)d_in[18];
    const float* c2b = (const float*)d_in[19];
    float* out = (float*)d_out;

    float *Kp, *Qp, *hattp, *t2p;
    __nv_bfloat16* Vbfp;
    cudaGetSymbolAddress((void**)&Kp, g_K);
    cudaGetSymbolAddress((void**)&Vbfp, g_Vbf);
    cudaGetSymbolAddress((void**)&Qp, g_Q);
    cudaGetSymbolAddress((void**)&hattp, g_hatt);
    cudaGetSymbolAddress((void**)&t2p, g_t2);

    prep_xp4<<<32, 256>>>(x_pkt);
    build_table_kernel<<<(TABN + 255) / 256, 256>>>(e1w, e1b, e2w, e2b);

    gemm64<false><<<dim3(NLIG / 64, HID / 64), 256>>>(h_lig, qw, qb, nullptr, Qp, NLIG, HID, HID);
    gemm64<false><<<dim3(NPKT / 64, HID / 64), 256>>>(h_atm, kw, kb, nullptr, Kp, NPKT, HID, ADIM);
    gemm64<true><<<dim3(NPKT / 64, HID / 64), 256>>>(h_atm, vw, vb, nullptr, Vbfp, NPKT, HID, ADIM);

    attn_kernel<<<NLIG, 256>>>(x_lig);

    // h_out = h_lig + h_att @ ow + ob   (written directly to out)
    gemm64<false><<<dim3(NLIG / 64, HID / 64), 256>>>(hattp, ow, ob, h_lig, out, NLIG, HID, HID);
    // t2 = h_att @ c1w + c1b
    gemm64<false><<<dim3(NLIG / 64, HID / 64), 256>>>(hattp, c1w, c1b, nullptr, t2p, NLIG, HID, HID);

    finalize_kernel<<<NLIG / 8, 256>>>(x_lig, c2w, c2b, out);
}

// round 3
// speedup vs baseline: 2.5955x; 1.5102x over previous
#include <cuda_runtime.h>
#include <cuda_bf16.h>
#include <math.h>
#include <stdint.h>

#define NLIG 1024
#define NPKT 8192
#define HID 256
#define ADIM 512
#define TABN 4096
#define CUTOFF 10.0f
#define CAP 2048

// ---------------- device scratch ----------------
__device__ __nv_bfloat16 g_Abf[NPKT * ADIM];    // h_atomica bf16
__device__ __nv_bfloat16 g_hligbf[NLIG * HID];  // h_lig bf16
__device__ __nv_bfloat16 g_kwbf[ADIM * HID];
__device__ __nv_bfloat16 g_vwbf[ADIM * HID];
__device__ __nv_bfloat16 g_qwbf[HID * HID];
__device__ __nv_bfloat16 g_Kbf[NPKT * HID];
__device__ __nv_bfloat16 g_Vbf[NPKT * HID];
__device__ float  g_Q[NLIG * HID];
__device__ float  g_hatt[NLIG * HID];
__device__ float  g_t2[NLIG * HID];
__device__ float4 g_cm[NLIG];
__device__ float4 g_xp4[NPKT];
__device__ float4 g_tab[TABN];

// ---------------- helpers ----------------
__device__ __forceinline__ float wsum(float v) {
    v += __shfl_xor_sync(0xffffffffu, v, 16);
    v += __shfl_xor_sync(0xffffffffu, v, 8);
    v += __shfl_xor_sync(0xffffffffu, v, 4);
    v += __shfl_xor_sync(0xffffffffu, v, 2);
    v += __shfl_xor_sync(0xffffffffu, v, 1);
    return v;
}
__device__ __forceinline__ float wmax(float v) {
    v = fmaxf(v, __shfl_xor_sync(0xffffffffu, v, 16));
    v = fmaxf(v, __shfl_xor_sync(0xffffffffu, v, 8));
    v = fmaxf(v, __shfl_xor_sync(0xffffffffu, v, 4));
    v = fmaxf(v, __shfl_xor_sync(0xffffffffu, v, 2));
    v = fmaxf(v, __shfl_xor_sync(0xffffffffu, v, 1));
    return v;
}
__device__ __forceinline__ uint32_t smem_u32(const void* p) {
    return (uint32_t)__cvta_generic_to_shared(p);
}

// ---------------- fp32 -> bf16 convert ----------------
__global__ void f2bf(const float* __restrict__ src, __nv_bfloat16* __restrict__ dst, int n) {
    int i = (blockIdx.x * 256 + threadIdx.x) * 4;
    if (i >= n) return;
    float4 v = *(const float4*)(src + i);
    __nv_bfloat162 p0 = __floats2bfloat162_rn(v.x, v.y);
    __nv_bfloat162 p1 = __floats2bfloat162_rn(v.z, v.w);
    *(__nv_bfloat162*)(dst + i) = p0;
    *(__nv_bfloat162*)(dst + i + 2) = p1;
}

// ---------------- x_pocket -> padded float4 ----------------
__global__ void prep_xp4(const float* __restrict__ xp) {
    int j = blockIdx.x * 256 + threadIdx.x;
    if (j < NPKT)
        g_xp4[j] = make_float4(xp[j * 3 + 0], xp[j * 3 + 1], xp[j * 3 + 2], 0.f);
}

// ---------------- edge-bias lookup table ----------------
__global__ void build_table_kernel(const float* __restrict__ e1w,
                                   const float* __restrict__ e1b,
                                   const float* __restrict__ e2w,
                                   const float* __restrict__ e2b) {
    int e = blockIdx.x * blockDim.x + threadIdx.x;
    if (e >= TABN) return;
    float d = (float)e * (CUTOFF / (float)(TABN - 1));
    float a0 = e2b[0], a1 = e2b[1], a2 = e2b[2], a3 = e2b[3];
    for (int u = 0; u < HID; u++) {
        float z = fmaf(d, e1w[u], e1b[u]);
        float s = z / (1.0f + expf(-z));
        a0 = fmaf(s, e2w[u * 4 + 0], a0);
        a1 = fmaf(s, e2w[u * 4 + 1], a1);
        a2 = fmaf(s, e2w[u * 4 + 2], a2);
        a3 = fmaf(s, e2w[u * 4 + 3], a3);
    }
    g_tab[e] = make_float4(a0, a1, a2, a3);
}

// ---------------- bf16 tensor-core GEMM: C = A@W + bias ----------------
// BM=128, BN=64, BK=32; 8 warps in 4(m) x 2(n); warp tile 32x32.
// A: MxK row-major bf16, W: KxN row-major bf16. Output float or bf16.
template <bool FLOATOUT>
__global__ __launch_bounds__(256) void gemm_mma(const __nv_bfloat16* __restrict__ A,
                                                const __nv_bfloat16* __restrict__ W,
                                                const float* __restrict__ bias,
                                                void* __restrict__ Cv,
                                                int M, int N, int K) {
    __shared__ __nv_bfloat16 As[128][40];  // pad: 80B row stride (conflict-free ldmatrix)
    __shared__ __nv_bfloat16 Bs[32][72];   // pad: 144B row stride
    const int t = threadIdx.x;
    const int warp = t >> 5, lane = t & 31;
    const int wm = warp >> 1, wn = warp & 1;
    const int bm = blockIdx.x * 128, bn = blockIdx.y * 64;

    float acc[2][4][4];
#pragma unroll
    for (int mt = 0; mt < 2; mt++)
#pragma unroll
        for (int nt = 0; nt < 4; nt++)
#pragma unroll
            for (int r = 0; r < 4; r++) acc[mt][nt][r] = 0.f;

    for (int kt = 0; kt < K; kt += 32) {
#pragma unroll
        for (int i = 0; i < 2; i++) {
            int s = t * 2 + i;
            int r = s >> 2, c = (s & 3) * 8;
            *(uint4*)&As[r][c] = *(const uint4*)(A + (size_t)(bm + r) * K + kt + c);
        }
        {
            int r = t >> 3, c = (t & 7) * 8;
            *(uint4*)&Bs[r][c] = *(const uint4*)(W + (size_t)(kt + r) * N + bn + c);
        }
        __syncthreads();
#pragma unroll
        for (int kk = 0; kk < 32; kk += 16) {
            uint32_t a[2][4];
#pragma unroll
            for (int mt = 0; mt < 2; mt++) {
                int row = wm * 32 + mt * 16 + (lane & 7) + 8 * ((lane >> 3) & 1);
                int col = kk + 8 * (lane >> 4);
                uint32_t addr = smem_u32(&As[row][col]);
                asm volatile("ldmatrix.sync.aligned.m8n8.x4.shared.b16 {%0,%1,%2,%3}, [%4];"
                             : "=r"(a[mt][0]), "=r"(a[mt][1]), "=r"(a[mt][2]), "=r"(a[mt][3])
                             : "r"(addr));
            }
            uint32_t b[4][2];
#pragma unroll
            for (int nt2 = 0; nt2 < 2; nt2++) {
                int row = kk + (lane & 7) + 8 * ((lane >> 3) & 1);
                int col = wn * 32 + nt2 * 16 + 8 * (lane >> 4);
                uint32_t addr = smem_u32(&Bs[row][col]);
                uint32_t b0, b1, b2, b3;
                asm volatile("ldmatrix.sync.aligned.m8n8.x4.trans.shared.b16 {%0,%1,%2,%3}, [%4];"
                             : "=r"(b0), "=r"(b1), "=r"(b2), "=r"(b3)
                             : "r"(addr));
                b[nt2 * 2 + 0][0] = b0; b[nt2 * 2 + 0][1] = b1;
                b[nt2 * 2 + 1][0] = b2; b[nt2 * 2 + 1][1] = b3;
            }
#pragma unroll
            for (int mt = 0; mt < 2; mt++)
#pragma unroll
                for (int nt = 0; nt < 4; nt++) {
                    asm volatile(
                        "mma.sync.aligned.m16n8k16.row.col.f32.bf16.bf16.f32 "
                        "{%0,%1,%2,%3}, {%4,%5,%6,%7}, {%8,%9}, {%0,%1,%2,%3};"
                        : "+f"(acc[mt][nt][0]), "+f"(acc[mt][nt][1]),
                          "+f"(acc[mt][nt][2]), "+f"(acc[mt][nt][3])
                        : "r"(a[mt][0]), "r"(a[mt][1]), "r"(a[mt][2]), "r"(a[mt][3]),
                          "r"(b[nt][0]), "r"(b[nt][1]));
                }
        }
        __syncthreads();
    }

#pragma unroll
    for (int mt = 0; mt < 2; mt++) {
#pragma unroll
        for (int nt = 0; nt < 4; nt++) {
            int row0 = bm + wm * 32 + mt * 16 + (lane >> 2);
            int col = bn + wn * 32 + nt * 8 + (lane & 3) * 2;
            float bi0 = bias[col], bi1 = bias[col + 1];
            float v0 = acc[mt][nt][0] + bi0, v1 = acc[mt][nt][1] + bi1;
            float v2 = acc[mt][nt][2] + bi0, v3 = acc[mt][nt][3] + bi1;
            if (FLOATOUT) {
                float* C = (float*)Cv;
                *(float2*)(C + (size_t)row0 * N + col) = make_float2(v0, v1);
                *(float2*)(C + (size_t)(row0 + 8) * N + col) = make_float2(v2, v3);
            } else {
                __nv_bfloat16* C = (__nv_bfloat16*)Cv;
                *(__nv_bfloat162*)(C + (size_t)row0 * N + col) = __floats2bfloat162_rn(v0, v1);
                *(__nv_bfloat162*)(C + (size_t)(row0 + 8) * N + col) = __floats2bfloat162_rn(v2, v3);
            }
        }
    }
}

// ---------------- 64x64x16 fp32 GEMM, bias + optional residual ----------------
__global__ __launch_bounds__(256) void gemm64(const float* __restrict__ A,
                                              const float* __restrict__ W,
                                              const float* __restrict__ bias,
                                              const float* __restrict__ R,
                                              float* __restrict__ C,
                                              int M, int N, int Kd) {
    __shared__ float As[64][16];
    __shared__ float Bs[16][64];
    const int t = threadIdx.x;
    const int tx = t & 15, ty = t >> 4;
    const int bm = blockIdx.x * 64, bn = blockIdx.y * 64;
    const int arow = t >> 2, ac4 = (t & 3) * 4;
    const int brow = t >> 4, bc4 = (t & 15) * 4;

    float acc[4][4];
#pragma unroll
    for (int i = 0; i < 4; i++)
#pragma unroll
        for (int j = 0; j < 4; j++) acc[i][j] = 0.f;

    for (int kt = 0; kt < Kd; kt += 16) {
        float4 av = *(const float4*)(A + (size_t)(bm + arow) * Kd + kt + ac4);
        float4 bv = *(const float4*)(W + (size_t)(kt + brow) * N + bn + bc4);
        *(float4*)&As[arow][ac4] = av;
        *(float4*)&Bs[brow][bc4] = bv;
        __syncthreads();
#pragma unroll
        for (int k = 0; k < 16; k++) {
            float4 bq = *(const float4*)&Bs[k][tx * 4];
            float a0 = As[ty * 4 + 0][k];
            float a1 = As[ty * 4 + 1][k];
            float a2 = As[ty * 4 + 2][k];
            float a3 = As[ty * 4 + 3][k];
            acc[0][0] = fmaf(a0, bq.x, acc[0][0]); acc[0][1] = fmaf(a0, bq.y, acc[0][1]);
            acc[0][2] = fmaf(a0, bq.z, acc[0][2]); acc[0][3] = fmaf(a0, bq.w, acc[0][3]);
            acc[1][0] = fmaf(a1, bq.x, acc[1][0]); acc[1][1] = fmaf(a1, bq.y, acc[1][1]);
            acc[1][2] = fmaf(a1, bq.z, acc[1][2]); acc[1][3] = fmaf(a1, bq.w, acc[1][3]);
            acc[2][0] = fmaf(a2, bq.x, acc[2][0]); acc[2][1] = fmaf(a2, bq.y, acc[2][1]);
            acc[2][2] = fmaf(a2, bq.z, acc[2][2]); acc[2][3] = fmaf(a2, bq.w, acc[2][3]);
            acc[3][0] = fmaf(a3, bq.x, acc[3][0]); acc[3][1] = fmaf(a3, bq.y, acc[3][1]);
            acc[3][2] = fmaf(a3, bq.z, acc[3][2]); acc[3][3] = fmaf(a3, bq.w, acc[3][3]);
        }
        __syncthreads();
    }

#pragma unroll
    for (int i = 0; i < 4; i++) {
        int row = bm + ty * 4 + i;
        int col = bn + tx * 4;
        float v0 = acc[i][0] + bias[col + 0];
        float v1 = acc[i][1] + bias[col + 1];
        float v2 = acc[i][2] + bias[col + 2];
        float v3 = acc[i][3] + bias[col + 3];
        if (R) {
            float4 r = *(const float4*)(R + (size_t)row * N + col);
            v0 += r.x; v1 += r.y; v2 += r.z; v3 += r.w;
        }
        *(float4*)(C + (size_t)row * N + col) = make_float4(v0, v1, v2, v3);
    }
}

// ---------------- attention kernel: one block per ligand ----------------
__global__ __launch_bounds__(256) void attn_kernel(const float* __restrict__ x_lig) {
    const int i = blockIdx.x;
    const int t = threadIdx.x;
    const int w = t >> 5, lane = t & 31;
    const int h = lane >> 3;

    __shared__ float q_s[HID];
    __shared__ unsigned short list[CAP];
    __shared__ float4 sarr[CAP];
    __shared__ float wv[8][HID];
    __shared__ float wred[8][4];
    __shared__ float wc[8][12];
    __shared__ float m_s[4], linv_s[4];
    __shared__ float c12[12];
    __shared__ int woff[8];
    __shared__ int s_cnt;
    __shared__ float s_xl[3];

    if (t < 3) s_xl[t] = x_lig[i * 3 + t];
    q_s[t] = g_Q[(size_t)i * HID + t];
    __syncthreads();
    const float xlx = s_xl[0], xly = s_xl[1], xlz = s_xl[2];

    // ---- Phase A: deterministic compaction ----
    unsigned msk = 0;
    const int jbase = t * 32;
#pragma unroll 4
    for (int k = 0; k < 32; k++) {
        float4 xp = g_xp4[jbase + k];
        float rx = xp.x - xlx, ry = xp.y - xly, rz = xp.z - xlz;
        float d = sqrtf(rx * rx + ry * ry + rz * rz);
        if (d < CUTOFF) msk |= (1u << k);
    }
    int mycnt = __popc(msk);
    int inc = mycnt;
#pragma unroll
    for (int off = 1; off < 32; off <<= 1) {
        int v = __shfl_up_sync(0xffffffffu, inc, off);
        if (lane >= off) inc += v;
    }
    if (lane == 31) woff[w] = inc;
    __syncthreads();
    if (t == 0) {
        int run = 0;
#pragma unroll
        for (int ww = 0; ww < 8; ww++) { int v = woff[ww]; woff[ww] = run; run += v; }
        s_cnt = run;
    }
    __syncthreads();
    int offset = woff[w] + (inc - mycnt);
    unsigned mm = msk;
    while (mm) {
        int k = __ffs(mm) - 1;
        mm &= mm - 1;
        if (offset < CAP) list[offset] = (unsigned short)(jbase + k);
        offset++;
    }
    __syncthreads();
    const int nact = (s_cnt < CAP) ? s_cnt : CAP;

    // ---- B1: warp-per-pair raw Q.K dots (K in bf16, one 512B row per warp) ----
    {
        const float4 qa = ((const float4*)q_s)[lane * 2];
        const float4 qb = ((const float4*)q_s)[lane * 2 + 1];
#pragma unroll 2
        for (int p = w; p < nact; p += 8) {
            const int jj = list[p];
            uint4 kr = *(const uint4*)(g_Kbf + (size_t)jj * HID + lane * 8);
            float2 k0 = __bfloat1622float2(*(__nv_bfloat162*)&kr.x);
            float2 k1 = __bfloat1622float2(*(__nv_bfloat162*)&kr.y);
            float2 k2 = __bfloat1622float2(*(__nv_bfloat162*)&kr.z);
            float2 k3 = __bfloat1622float2(*(__nv_bfloat162*)&kr.w);
            float dp = qa.x * k0.x + qa.y * k0.y + qa.z * k1.x + qa.w * k1.y +
                       qb.x * k2.x + qb.y * k2.y + qb.z * k3.x + qb.w * k3.y;
            dp += __shfl_xor_sync(0xffffffffu, dp, 1);
            dp += __shfl_xor_sync(0xffffffffu, dp, 2);
            dp += __shfl_xor_sync(0xffffffffu, dp, 4);
            float s0 = __shfl_sync(0xffffffffu, dp, 0);
            float s1 = __shfl_sync(0xffffffffu, dp, 8);
            float s2 = __shfl_sync(0xffffffffu, dp, 16);
            float s3 = __shfl_sync(0xffffffffu, dp, 24);
            if (lane == 0) sarr[p] = make_float4(s0, s1, s2, s3);
        }
    }
    __syncthreads();

    // ---- B2a pass 1: scale + edge bias, block max ----
    float mx0 = -INFINITY, mx1 = -INFINITY, mx2 = -INFINITY, mx3 = -INFINITY;
    for (int p = t; p < nact; p += 256) {
        float4 s = sarr[p];
        const int jj = list[p];
        float4 xp = g_xp4[jj];
        float rx = xp.x - xlx, ry = xp.y - xly, rz = xp.z - xlz;
        float d = sqrtf(rx * rx + ry * ry + rz * rz);
        float tp = d * ((float)(TABN - 1) / CUTOFF);
        int k0 = (int)tp;
        k0 = (k0 > TABN - 2) ? (TABN - 2) : k0;
        float fr = tp - (float)k0;
        float4 f0 = g_tab[k0], f1 = g_tab[k0 + 1];
        s.x = fmaf(s.x, 0.125f, f0.x + fr * (f1.x - f0.x));
        s.y = fmaf(s.y, 0.125f, f0.y + fr * (f1.y - f0.y));
        s.z = fmaf(s.z, 0.125f, f0.z + fr * (f1.z - f0.z));
        s.w = fmaf(s.w, 0.125f, f0.w + fr * (f1.w - f0.w));
        sarr[p] = s;
        mx0 = fmaxf(mx0, s.x); mx1 = fmaxf(mx1, s.y);
        mx2 = fmaxf(mx2, s.z); mx3 = fmaxf(mx3, s.w);
    }
    mx0 = wmax(mx0); mx1 = wmax(mx1); mx2 = wmax(mx2); mx3 = wmax(mx3);
    if (lane == 0) { wred[w][0] = mx0; wred[w][1] = mx1; wred[w][2] = mx2; wred[w][3] = mx3; }
    __syncthreads();
    if (t < 4) {
        float m = -INFINITY;
#pragma unroll
        for (int w2 = 0; w2 < 8; w2++) m = fmaxf(m, wred[w2][t]);
        m_s[t] = m;
    }
    __syncthreads();
    const float m0 = m_s[0], m1 = m_s[1], m2 = m_s[2], m3 = m_s[3];

    // ---- B2a pass 2: exp, l-sums, coord sums ----
    float l0 = 0.f, l1 = 0.f, l2 = 0.f, l3 = 0.f;
    float c[12];
#pragma unroll
    for (int j = 0; j < 12; j++) c[j] = 0.f;
    for (int p = t; p < nact; p += 256) {
        float4 s = sarr[p];
        float p0 = __expf(s.x - m0);
        float p1 = __expf(s.y - m1);
        float p2 = __expf(s.z - m2);
        float p3 = __expf(s.w - m3);
        sarr[p] = make_float4(p0, p1, p2, p3);
        l0 += p0; l1 += p1; l2 += p2; l3 += p3;
        const int jj = list[p];
        float4 xp = g_xp4[jj];
        float rx = xp.x - xlx, ry = xp.y - xly, rz = xp.z - xlz;
        float d = sqrtf(rx * rx + ry * ry + rz * rz);
        float invd = __fdividef(1.0f, d + 1e-8f);
        float nrx = rx * invd, nry = ry * invd, nrz = rz * invd;
        c[0] = fmaf(p0, nrx, c[0]); c[1]  = fmaf(p0, nry, c[1]);  c[2]  = fmaf(p0, nrz, c[2]);
        c[3] = fmaf(p1, nrx, c[3]); c[4]  = fmaf(p1, nry, c[4]);  c[5]  = fmaf(p1, nrz, c[5]);
        c[6] = fmaf(p2, nrx, c[6]); c[7]  = fmaf(p2, nry, c[7]);  c[8]  = fmaf(p2, nrz, c[8]);
        c[9] = fmaf(p3, nrx, c[9]); c[10] = fmaf(p3, nry, c[10]); c[11] = fmaf(p3, nrz, c[11]);
    }
    l0 = wsum(l0); l1 = wsum(l1); l2 = wsum(l2); l3 = wsum(l3);
#pragma unroll
    for (int j = 0; j < 12; j++) c[j] = wsum(c[j]);
    if (lane == 0) {
        wred[w][0] = l0; wred[w][1] = l1; wred[w][2] = l2; wred[w][3] = l3;
#pragma unroll
        for (int j = 0; j < 12; j++) wc[w][j] = c[j];
    }
    __syncthreads();
    if (t < 4) {
        float L = 0.f;
#pragma unroll
        for (int w2 = 0; w2 < 8; w2++) L += wred[w2][t];
        linv_s[t] = (L > 0.f) ? __fdividef(1.0f, L) : 0.f;
    }
    if (t >= 32 && t < 44) {
        int j = t - 32;
        float cc = 0.f;
#pragma unroll
        for (int w2 = 0; w2 < 8; w2++) cc += wc[w2][j];
        c12[j] = cc;
    }
    __syncthreads();
    if (t < 3) {
        float v = 0.f;
#pragma unroll
        for (int h2 = 0; h2 < 4; h2++) v += c12[h2 * 3 + t] * linv_s[h2];
        ((float*)&g_cm[i])[t] = 0.25f * v;
    }

    // ---- B2b: warp-per-pair weighted V accumulation (bf16 V) ----
    float av[8];
#pragma unroll
    for (int k = 0; k < 8; k++) av[k] = 0.f;
    const float* pef = (const float*)sarr;
#pragma unroll 2
    for (int p = w; p < nact; p += 8) {
        const int jj = list[p];
        float pe = pef[p * 4 + h];
        uint4 vr = *(const uint4*)(g_Vbf + (size_t)jj * HID + lane * 8);
        float2 v0 = __bfloat1622float2(*(__nv_bfloat162*)&vr.x);
        float2 v1 = __bfloat1622float2(*(__nv_bfloat162*)&vr.y);
        float2 v2 = __bfloat1622float2(*(__nv_bfloat162*)&vr.z);
        float2 v3 = __bfloat1622float2(*(__nv_bfloat162*)&vr.w);
        av[0] = fmaf(pe, v0.x, av[0]); av[1] = fmaf(pe, v0.y, av[1]);
        av[2] = fmaf(pe, v1.x, av[2]); av[3] = fmaf(pe, v1.y, av[3]);
        av[4] = fmaf(pe, v2.x, av[4]); av[5] = fmaf(pe, v2.y, av[5]);
        av[6] = fmaf(pe, v3.x, av[6]); av[7] = fmaf(pe, v3.y, av[7]);
    }
#pragma unroll
    for (int k = 0; k < 8; k++) wv[w][lane * 8 + k] = av[k];
    __syncthreads();
    {
        float hv = 0.f;
#pragma unroll
        for (int w2 = 0; w2 < 8; w2++) hv += wv[w2][t];
        g_hatt[(size_t)i * HID + t] = hv * linv_s[t >> 6];
    }
}

// ---------------- finalize: coord scale + x_out ----------------
__global__ __launch_bounds__(256) void finalize_kernel(const float* __restrict__ x_lig,
                                                       const float* __restrict__ c2w,
                                                       const float* __restrict__ c2b,
                                                       float* __restrict__ out) {
    const int lig = blockIdx.x * 8 + (threadIdx.x >> 5);
    const int lane = threadIdx.x & 31;
    const float4* t2 = (const float4*)(g_t2 + (size_t)lig * HID) + lane * 2;
    float4 a = t2[0], b = t2[1];
    const float4* cw = (const float4*)c2w + lane * 2;
    float4 ca = cw[0], cb = cw[1];
    float s = 0.f;
    s = fmaf(a.x / (1.f + __expf(-a.x)), ca.x, s);
    s = fmaf(a.y / (1.f + __expf(-a.y)), ca.y, s);
    s = fmaf(a.z / (1.f + __expf(-a.z)), ca.z, s);
    s = fmaf(a.w / (1.f + __expf(-a.w)), ca.w, s);
    s = fmaf(b.x / (1.f + __expf(-b.x)), cb.x, s);
    s = fmaf(b.y / (1.f + __expf(-b.y)), cb.y, s);
    s = fmaf(b.z / (1.f + __expf(-b.z)), cb.z, s);
    s = fmaf(b.w / (1.f + __expf(-b.w)), cb.w, s);
    s = wsum(s);
    if (lane == 0) {
        s += c2b[0];
        float4 cm = g_cm[lig];
        float* ox = out + (size_t)NLIG * HID + lig * 3;
        ox[0] = x_lig[lig * 3 + 0] + s * cm.x;
        ox[1] = x_lig[lig * 3 + 1] + s * cm.y;
        ox[2] = x_lig[lig * 3 + 2] + s * cm.z;
    }
}

// ---------------- launch ----------------
extern "C" void kernel_launch(void* const* d_in, const int* in_sizes, int n_in,
                              void* d_out, int out_size) {
    const float* h_lig = (const float*)d_in[0];
    const float* x_lig = (const float*)d_in[1];
    const float* h_atm = (const float*)d_in[2];
    const float* x_pkt = (const float*)d_in[3];
    const float* qw = (const float*)d_in[4];
    const float* qb = (const float*)d_in[5];
    const float* kw = (const float*)d_in[6];
    const float* kb = (const float*)d_in[7];
    const float* vw = (const float*)d_in[8];
    const float* vb = (const float*)d_in[9];
    const float* ow = (const float*)d_in[10];
    const float* ob = (const float*)d_in[11];
    const float* e1w = (const float*)d_in[12];
    const float* e1b = (const float*)d_in[13];
    const float* e2w = (const float*)d_in[14];
    const float* e2b = (const float*)d_in[15];
    const float* c1w = (const float*)d_in[16];
    const float* c1b = (const float*)d_in[17];
    const float* c2w = (const float*)d_in[18];
    const float* c2b = (const float*)d_in[19];
    float* out = (float*)d_out;

    __nv_bfloat16 *Abf, *hligbf, *kwbf, *vwbf, *qwbf, *Kbf, *Vbf;
    float *Qp, *hattp, *t2p;
    cudaGetSymbolAddress((void**)&Abf, g_Abf);
    cudaGetSymbolAddress((void**)&hligbf, g_hligbf);
    cudaGetSymbolAddress((void**)&kwbf, g_kwbf);
    cudaGetSymbolAddress((void**)&vwbf, g_vwbf);
    cudaGetSymbolAddress((void**)&qwbf, g_qwbf);
    cudaGetSymbolAddress((void**)&Kbf, g_Kbf);
    cudaGetSymbolAddress((void**)&Vbf, g_Vbf);
    cudaGetSymbolAddress((void**)&Qp, g_Q);
    cudaGetSymbolAddress((void**)&hattp, g_hatt);
    cudaGetSymbolAddress((void**)&t2p, g_t2);

    prep_xp4<<<32, 256>>>(x_pkt);
    build_table_kernel<<<(TABN + 255) / 256, 256>>>(e1w, e1b, e2w, e2b);

    // fp32 -> bf16 conversions
    f2bf<<<(NPKT * ADIM) / 1024, 256>>>(h_atm, Abf, NPKT * ADIM);
    f2bf<<<(NLIG * HID) / 1024, 256>>>(h_lig, hligbf, NLIG * HID);
    f2bf<<<(ADIM * HID) / 1024, 256>>>(kw, kwbf, ADIM * HID);
    f2bf<<<(ADIM * HID) / 1024, 256>>>(vw, vwbf, ADIM * HID);
    f2bf<<<(HID * HID) / 1024, 256>>>(qw, qwbf, HID * HID);

    // tensor-core projections
    gemm_mma<true><<<dim3(NLIG / 128, HID / 64), 256>>>(hligbf, qwbf, qb, Qp, NLIG, HID, HID);
    gemm_mma<false><<<dim3(NPKT / 128, HID / 64), 256>>>(Abf, kwbf, kb, Kbf, NPKT, HID, ADIM);
    gemm_mma<false><<<dim3(NPKT / 128, HID / 64), 256>>>(Abf, vwbf, vb, Vbf, NPKT, HID, ADIM);

    attn_kernel<<<NLIG, 256>>>(x_lig);

    // h_out = h_lig + h_att @ ow + ob
    gemm64<<<dim3(NLIG / 64, HID / 64), 256>>>(hattp, ow, ob, h_lig, out, NLIG, HID, HID);
    // t2 = h_att @ c1w + c1b
    gemm64<<<dim3(NLIG / 64, HID / 64), 256>>>(hattp, c1w, c1b, nullptr, t2p, NLIG, HID, HID);

    finalize_kernel<<<NLIG / 8, 256>>>(x_lig, c2w, c2b, out);
}

// round 4
// speedup vs baseline: 2.7664x; 1.0658x over previous
#include <cuda_runtime.h>
#include <cuda_bf16.h>
#include <math.h>
#include <stdint.h>

#define NLIG 1024
#define NPKT 8192
#define HID 256
#define ADIM 512
#define TABN 4096
#define CUTOFF 10.0f
#define CAP 1536

// ---------------- device scratch ----------------
__device__ __nv_bfloat16 g_Abf[NPKT * ADIM];
__device__ __nv_bfloat16 g_hligbf[NLIG * HID];
__device__ __nv_bfloat16 g_kwbf[ADIM * HID];
__device__ __nv_bfloat16 g_vwbf[ADIM * HID];
__device__ __nv_bfloat16 g_qwbf[HID * HID];
__device__ __nv_bfloat16 g_Kbf[NPKT * HID];
__device__ __nv_bfloat16 g_Vbf[NPKT * HID];
__device__ float  g_Q[NLIG * HID];
__device__ float  g_hatt[NLIG * HID];
__device__ float  g_t2[NLIG * HID];
__device__ float4 g_cm[NLIG];
__device__ float4 g_xp4[NPKT];
__device__ float4 g_tab[TABN];

// ---------------- helpers ----------------
__device__ __forceinline__ float wsum(float v) {
    v += __shfl_xor_sync(0xffffffffu, v, 16);
    v += __shfl_xor_sync(0xffffffffu, v, 8);
    v += __shfl_xor_sync(0xffffffffu, v, 4);
    v += __shfl_xor_sync(0xffffffffu, v, 2);
    v += __shfl_xor_sync(0xffffffffu, v, 1);
    return v;
}
__device__ __forceinline__ float wmax(float v) {
    v = fmaxf(v, __shfl_xor_sync(0xffffffffu, v, 16));
    v = fmaxf(v, __shfl_xor_sync(0xffffffffu, v, 8));
    v = fmaxf(v, __shfl_xor_sync(0xffffffffu, v, 4));
    v = fmaxf(v, __shfl_xor_sync(0xffffffffu, v, 2));
    v = fmaxf(v, __shfl_xor_sync(0xffffffffu, v, 1));
    return v;
}
__device__ __forceinline__ uint32_t smem_u32(const void* p) {
    return (uint32_t)__cvta_generic_to_shared(p);
}

// ---------------- fused prep: table (blocks 0-15) + xp4 (blocks 16-47) ----
__global__ void prep_misc(const float* __restrict__ xp,
                          const float* __restrict__ e1w,
                          const float* __restrict__ e1b,
                          const float* __restrict__ e2w,
                          const float* __restrict__ e2b) {
    int b = blockIdx.x, t = threadIdx.x;
    if (b < 16) {
        int e = b * 256 + t;
        float d = (float)e * (CUTOFF / (float)(TABN - 1));
        float a0 = e2b[0], a1 = e2b[1], a2 = e2b[2], a3 = e2b[3];
        for (int u = 0; u < HID; u++) {
            float z = fmaf(d, e1w[u], e1b[u]);
            float s = z / (1.0f + expf(-z));
            a0 = fmaf(s, e2w[u * 4 + 0], a0);
            a1 = fmaf(s, e2w[u * 4 + 1], a1);
            a2 = fmaf(s, e2w[u * 4 + 2], a2);
            a3 = fmaf(s, e2w[u * 4 + 3], a3);
        }
        g_tab[e] = make_float4(a0, a1, a2, a3);
    } else {
        int j = (b - 16) * 256 + t;
        g_xp4[j] = make_float4(xp[j * 3 + 0], xp[j * 3 + 1], xp[j * 3 + 2], 0.f);
    }
}

// ---------------- fused fp32 -> bf16 for all 5 arrays ----------------
#define SZ0 (NPKT * ADIM)                 // 4194304
#define SZ1 (SZ0 + NLIG * HID)            // 4456448
#define SZ2 (SZ1 + ADIM * HID)            // 4587520
#define SZ3 (SZ2 + ADIM * HID)            // 4718592
#define SZ4 (SZ3 + HID * HID)             // 4784128
__global__ void f2bf_all(const float* __restrict__ h_atm, const float* __restrict__ h_lig,
                         const float* __restrict__ kw, const float* __restrict__ vw,
                         const float* __restrict__ qw) {
    long i4 = (long)(blockIdx.x * 256 + threadIdx.x) * 4;
    const float* src;
    __nv_bfloat16* dst;
    long off;
    if (i4 < SZ0)      { src = h_atm; dst = g_Abf;    off = i4; }
    else if (i4 < SZ1) { src = h_lig; dst = g_hligbf; off = i4 - SZ0; }
    else if (i4 < SZ2) { src = kw;    dst = g_kwbf;   off = i4 - SZ1; }
    else if (i4 < SZ3) { src = vw;    dst = g_vwbf;   off = i4 - SZ2; }
    else if (i4 < SZ4) { src = qw;    dst = g_qwbf;   off = i4 - SZ3; }
    else return;
    float4 v = *(const float4*)(src + off);
    *(__nv_bfloat162*)(dst + off)     = __floats2bfloat162_rn(v.x, v.y);
    *(__nv_bfloat162*)(dst + off + 2) = __floats2bfloat162_rn(v.z, v.w);
}

// ---------------- bf16 tensor-core GEMM: C = A@W + bias ----------------
// BM=64, BN=64, BK=32; 8 warps in 4(m) x 2(n); warp tile 16x32.
template <bool FLOATOUT>
__global__ __launch_bounds__(256) void gemm_mma(const __nv_bfloat16* __restrict__ A,
                                                const __nv_bfloat16* __restrict__ W,
                                                const float* __restrict__ bias,
                                                void* __restrict__ Cv,
                                                int M, int N, int K) {
    __shared__ __nv_bfloat16 As[64][40];
    __shared__ __nv_bfloat16 Bs[32][72];
    const int t = threadIdx.x;
    const int warp = t >> 5, lane = t & 31;
    const int wm = warp >> 1, wn = warp & 1;
    const int bm = blockIdx.x * 64, bn = blockIdx.y * 64;

    float acc[4][4];
#pragma unroll
    for (int nt = 0; nt < 4; nt++)
#pragma unroll
        for (int r = 0; r < 4; r++) acc[nt][r] = 0.f;

    for (int kt = 0; kt < K; kt += 32) {
        {
            int r = t >> 2, c = (t & 3) * 8;
            *(uint4*)&As[r][c] = *(const uint4*)(A + (size_t)(bm + r) * K + kt + c);
        }
        {
            int r = t >> 3, c = (t & 7) * 8;
            *(uint4*)&Bs[r][c] = *(const uint4*)(W + (size_t)(kt + r) * N + bn + c);
        }
        __syncthreads();
#pragma unroll
        for (int kk = 0; kk < 32; kk += 16) {
            uint32_t a[4];
            {
                int row = wm * 16 + (lane & 15);
                int col = kk + 8 * (lane >> 4);
                uint32_t addr = smem_u32(&As[row][col]);
                asm volatile("ldmatrix.sync.aligned.m8n8.x4.shared.b16 {%0,%1,%2,%3}, [%4];"
                             : "=r"(a[0]), "=r"(a[1]), "=r"(a[2]), "=r"(a[3])
                             : "r"(addr));
            }
            uint32_t b[4][2];
#pragma unroll
            for (int nt2 = 0; nt2 < 2; nt2++) {
                int row = kk + (lane & 15);
                int col = wn * 32 + nt2 * 16 + 8 * (lane >> 4);
                uint32_t addr = smem_u32(&Bs[row][col]);
                uint32_t b0, b1, b2, b3;
                asm volatile("ldmatrix.sync.aligned.m8n8.x4.trans.shared.b16 {%0,%1,%2,%3}, [%4];"
                             : "=r"(b0), "=r"(b1), "=r"(b2), "=r"(b3)
                             : "r"(addr));
                b[nt2 * 2 + 0][0] = b0; b[nt2 * 2 + 0][1] = b1;
                b[nt2 * 2 + 1][0] = b2; b[nt2 * 2 + 1][1] = b3;
            }
#pragma unroll
            for (int nt = 0; nt < 4; nt++) {
                asm volatile(
                    "mma.sync.aligned.m16n8k16.row.col.f32.bf16.bf16.f32 "
                    "{%0,%1,%2,%3}, {%4,%5,%6,%7}, {%8,%9}, {%0,%1,%2,%3};"
                    : "+f"(acc[nt][0]), "+f"(acc[nt][1]), "+f"(acc[nt][2]), "+f"(acc[nt][3])
                    : "r"(a[0]), "r"(a[1]), "r"(a[2]), "r"(a[3]),
                      "r"(b[nt][0]), "r"(b[nt][1]));
            }
        }
        __syncthreads();
    }

#pragma unroll
    for (int nt = 0; nt < 4; nt++) {
        int row0 = bm + wm * 16 + (lane >> 2);
        int col = bn + wn * 32 + nt * 8 + (lane & 3) * 2;
        float bi0 = bias[col], bi1 = bias[col + 1];
        float v0 = acc[nt][0] + bi0, v1 = acc[nt][1] + bi1;
        float v2 = acc[nt][2] + bi0, v3 = acc[nt][3] + bi1;
        if (FLOATOUT) {
            float* C = (float*)Cv;
            *(float2*)(C + (size_t)row0 * N + col) = make_float2(v0, v1);
            *(float2*)(C + (size_t)(row0 + 8) * N + col) = make_float2(v2, v3);
        } else {
            __nv_bfloat16* C = (__nv_bfloat16*)Cv;
            *(__nv_bfloat162*)(C + (size_t)row0 * N + col) = __floats2bfloat162_rn(v0, v1);
            *(__nv_bfloat162*)(C + (size_t)(row0 + 8) * N + col) = __floats2bfloat162_rn(v2, v3);
        }
    }
}

// ---------------- 64x64x16 fp32 GEMM, bias + optional residual ----------------
__global__ __launch_bounds__(256) void gemm64(const float* __restrict__ A,
                                              const float* __restrict__ W,
                                              const float* __restrict__ bias,
                                              const float* __restrict__ R,
                                              float* __restrict__ C,
                                              int M, int N, int Kd) {
    __shared__ float As[64][16];
    __shared__ float Bs[16][64];
    const int t = threadIdx.x;
    const int tx = t & 15, ty = t >> 4;
    const int bm = blockIdx.x * 64, bn = blockIdx.y * 64;
    const int arow = t >> 2, ac4 = (t & 3) * 4;
    const int brow = t >> 4, bc4 = (t & 15) * 4;

    float acc[4][4];
#pragma unroll
    for (int i = 0; i < 4; i++)
#pragma unroll
        for (int j = 0; j < 4; j++) acc[i][j] = 0.f;

    for (int kt = 0; kt < Kd; kt += 16) {
        float4 av = *(const float4*)(A + (size_t)(bm + arow) * Kd + kt + ac4);
        float4 bv = *(const float4*)(W + (size_t)(kt + brow) * N + bn + bc4);
        *(float4*)&As[arow][ac4] = av;
        *(float4*)&Bs[brow][bc4] = bv;
        __syncthreads();
#pragma unroll
        for (int k = 0; k < 16; k++) {
            float4 bq = *(const float4*)&Bs[k][tx * 4];
            float a0 = As[ty * 4 + 0][k];
            float a1 = As[ty * 4 + 1][k];
            float a2 = As[ty * 4 + 2][k];
            float a3 = As[ty * 4 + 3][k];
            acc[0][0] = fmaf(a0, bq.x, acc[0][0]); acc[0][1] = fmaf(a0, bq.y, acc[0][1]);
            acc[0][2] = fmaf(a0, bq.z, acc[0][2]); acc[0][3] = fmaf(a0, bq.w, acc[0][3]);
            acc[1][0] = fmaf(a1, bq.x, acc[1][0]); acc[1][1] = fmaf(a1, bq.y, acc[1][1]);
            acc[1][2] = fmaf(a1, bq.z, acc[1][2]); acc[1][3] = fmaf(a1, bq.w, acc[1][3]);
            acc[2][0] = fmaf(a2, bq.x, acc[2][0]); acc[2][1] = fmaf(a2, bq.y, acc[2][1]);
            acc[2][2] = fmaf(a2, bq.z, acc[2][2]); acc[2][3] = fmaf(a2, bq.w, acc[2][3]);
            acc[3][0] = fmaf(a3, bq.x, acc[3][0]); acc[3][1] = fmaf(a3, bq.y, acc[3][1]);
            acc[3][2] = fmaf(a3, bq.z, acc[3][2]); acc[3][3] = fmaf(a3, bq.w, acc[3][3]);
        }
        __syncthreads();
    }

#pragma unroll
    for (int i = 0; i < 4; i++) {
        int row = bm + ty * 4 + i;
        int col = bn + tx * 4;
        float v0 = acc[i][0] + bias[col + 0];
        float v1 = acc[i][1] + bias[col + 1];
        float v2 = acc[i][2] + bias[col + 2];
        float v3 = acc[i][3] + bias[col + 3];
        if (R) {
            float4 r = *(const float4*)(R + (size_t)row * N + col);
            v0 += r.x; v1 += r.y; v2 += r.z; v3 += r.w;
        }
        *(float4*)(C + (size_t)row * N + col) = make_float4(v0, v1, v2, v3);
    }
}

// ---------------- attention kernel: one block per ligand ----------------
__global__ __launch_bounds__(256, 5) void attn_kernel(const float* __restrict__ x_lig) {
    const int i = blockIdx.x;
    const int t = threadIdx.x;
    const int w = t >> 5, lane = t & 31;
    const int h = lane >> 3;

    __shared__ float q_s[HID];
    __shared__ unsigned short list[CAP];
    __shared__ float4 sarr[CAP];
    __shared__ float wv[8][HID];
    __shared__ float wred[8][4];
    __shared__ float wc[8][4];
    __shared__ float m_s[4], linv_s[4];
    __shared__ float c12[12];
    __shared__ int woff[8];
    __shared__ int s_cnt;
    __shared__ float s_xl[3];

    if (t < 3) s_xl[t] = x_lig[i * 3 + t];
    q_s[t] = g_Q[(size_t)i * HID + t] * 0.125f;  // fold 1/sqrt(HEAD_DIM)
    __syncthreads();
    const float xlx = s_xl[0], xly = s_xl[1], xlz = s_xl[2];

    // ---- Phase A: deterministic compaction ----
    unsigned msk = 0;
    const int jbase = t * 32;
#pragma unroll 4
    for (int k = 0; k < 32; k++) {
        float4 xp = g_xp4[jbase + k];
        float rx = xp.x - xlx, ry = xp.y - xly, rz = xp.z - xlz;
        float d2 = rx * rx + ry * ry + rz * rz;
        if (d2 < CUTOFF * CUTOFF) msk |= (1u << k);
    }
    int mycnt = __popc(msk);
    int inc = mycnt;
#pragma unroll
    for (int off = 1; off < 32; off <<= 1) {
        int v = __shfl_up_sync(0xffffffffu, inc, off);
        if (lane >= off) inc += v;
    }
    if (lane == 31) woff[w] = inc;
    __syncthreads();
    if (t == 0) {
        int run = 0;
#pragma unroll
        for (int ww = 0; ww < 8; ww++) { int v = woff[ww]; woff[ww] = run; run += v; }
        s_cnt = run;
    }
    __syncthreads();
    int offset = woff[w] + (inc - mycnt);
    unsigned mm = msk;
    while (mm) {
        int k = __ffs(mm) - 1;
        mm &= mm - 1;
        if (offset < CAP) list[offset] = (unsigned short)(jbase + k);
        offset++;
    }
    __syncthreads();
    const int nact = (s_cnt < CAP) ? s_cnt : CAP;

    // ---- B1: warp-per-pair raw Q.K dots (Q pre-scaled) ----
    {
        const float4 qa = ((const float4*)q_s)[lane * 2];
        const float4 qb = ((const float4*)q_s)[lane * 2 + 1];
        float* sf = (float*)sarr;
#pragma unroll 2
        for (int p = w; p < nact; p += 8) {
            const int jj = list[p];
            uint4 kr = *(const uint4*)(g_Kbf + (size_t)jj * HID + lane * 8);
            float2 k0 = __bfloat1622float2(*(__nv_bfloat162*)&kr.x);
            float2 k1 = __bfloat1622float2(*(__nv_bfloat162*)&kr.y);
            float2 k2 = __bfloat1622float2(*(__nv_bfloat162*)&kr.z);
            float2 k3 = __bfloat1622float2(*(__nv_bfloat162*)&kr.w);
            float dp = qa.x * k0.x + qa.y * k0.y + qa.z * k1.x + qa.w * k1.y +
                       qb.x * k2.x + qb.y * k2.y + qb.z * k3.x + qb.w * k3.y;
            dp += __shfl_xor_sync(0xffffffffu, dp, 1);
            dp += __shfl_xor_sync(0xffffffffu, dp, 2);
            dp += __shfl_xor_sync(0xffffffffu, dp, 4);
            if ((lane & 7) == 0) sf[p * 4 + (lane >> 3)] = dp;
        }
    }
    __syncthreads();

    // ---- B2a pass 1: thread-per-pair edge bias + block max ----
    float mx0 = -INFINITY, mx1 = -INFINITY, mx2 = -INFINITY, mx3 = -INFINITY;
    for (int p = t; p < nact; p += 256) {
        float4 s = sarr[p];
        const int jj = list[p];
        float4 xp = g_xp4[jj];
        float rx = xp.x - xlx, ry = xp.y - xly, rz = xp.z - xlz;
        float d = sqrtf(rx * rx + ry * ry + rz * rz);
        float tp = d * ((float)(TABN - 1) / CUTOFF);
        int k0 = (int)tp;
        k0 = (k0 > TABN - 2) ? (TABN - 2) : k0;
        float fr = tp - (float)k0;
        float4 f0 = g_tab[k0], f1 = g_tab[k0 + 1];
        s.x += f0.x + fr * (f1.x - f0.x);
        s.y += f0.y + fr * (f1.y - f0.y);
        s.z += f0.z + fr * (f1.z - f0.z);
        s.w += f0.w + fr * (f1.w - f0.w);
        sarr[p] = s;
        mx0 = fmaxf(mx0, s.x); mx1 = fmaxf(mx1, s.y);
        mx2 = fmaxf(mx2, s.z); mx3 = fmaxf(mx3, s.w);
    }
    mx0 = wmax(mx0); mx1 = wmax(mx1); mx2 = wmax(mx2); mx3 = wmax(mx3);
    if (lane == 0) { wred[w][0] = mx0; wred[w][1] = mx1; wred[w][2] = mx2; wred[w][3] = mx3; }
    __syncthreads();
    if (t < 4) {
        float m = -INFINITY;
#pragma unroll
        for (int w2 = 0; w2 < 8; w2++) m = fmaxf(m, wred[w2][t]);
        m_s[t] = m;
    }
    __syncthreads();

    // ---- B2a pass 2: warp-per-head exp + l-sums + coord sums ----
    {
        const int hh = w & 3;
        const int half = w >> 2;
        const float mh = m_s[hh];
        float* sf = (float*)sarr;
        float l = 0.f, cx = 0.f, cy = 0.f, cz = 0.f;
        for (int p = half * 32 + lane; p < nact; p += 64) {
            float s = sf[p * 4 + hh];
            float pe = __expf(s - mh);
            sf[p * 4 + hh] = pe;
            l += pe;
            const int jj = list[p];
            float4 xp = g_xp4[jj];
            float rx = xp.x - xlx, ry = xp.y - xly, rz = xp.z - xlz;
            float d2 = rx * rx + ry * ry + rz * rz;
            float invd = rsqrtf(d2 + 1e-16f);
            float pin = pe * invd;
            cx = fmaf(pin, rx, cx); cy = fmaf(pin, ry, cy); cz = fmaf(pin, rz, cz);
        }
        l = wsum(l); cx = wsum(cx); cy = wsum(cy); cz = wsum(cz);
        if (lane == 0) {
            wred[w][0] = l;
            wc[w][0] = cx; wc[w][1] = cy; wc[w][2] = cz;
        }
    }
    __syncthreads();
    if (t < 4) {
        float L = wred[t][0] + wred[t + 4][0];
        linv_s[t] = (L > 0.f) ? __fdividef(1.0f, L) : 0.f;
    }
    if (t >= 32 && t < 44) {
        int j = t - 32;
        int h2 = j / 3, ax = j % 3;
        c12[j] = wc[h2][ax] + wc[h2 + 4][ax];
    }
    __syncthreads();
    if (t < 3) {
        float v = 0.f;
#pragma unroll
        for (int h2 = 0; h2 < 4; h2++) v += c12[h2 * 3 + t] * linv_s[h2];
        ((float*)&g_cm[i])[t] = 0.25f * v;
    }

    // ---- B2b: warp-per-pair weighted V accumulation (bf16 V) ----
    float av[8];
#pragma unroll
    for (int k = 0; k < 8; k++) av[k] = 0.f;
    const float* pef = (const float*)sarr;
#pragma unroll 2
    for (int p = w; p < nact; p += 8) {
        const int jj = list[p];
        float pe = pef[p * 4 + h];
        uint4 vr = *(const uint4*)(g_Vbf + (size_t)jj * HID + lane * 8);
        float2 v0 = __bfloat1622float2(*(__nv_bfloat162*)&vr.x);
        float2 v1 = __bfloat1622float2(*(__nv_bfloat162*)&vr.y);
        float2 v2 = __bfloat1622float2(*(__nv_bfloat162*)&vr.z);
        float2 v3 = __bfloat1622float2(*(__nv_bfloat162*)&vr.w);
        av[0] = fmaf(pe, v0.x, av[0]); av[1] = fmaf(pe, v0.y, av[1]);
        av[2] = fmaf(pe, v1.x, av[2]); av[3] = fmaf(pe, v1.y, av[3]);
        av[4] = fmaf(pe, v2.x, av[4]); av[5] = fmaf(pe, v2.y, av[5]);
        av[6] = fmaf(pe, v3.x, av[6]); av[7] = fmaf(pe, v3.y, av[7]);
    }
#pragma unroll
    for (int k = 0; k < 8; k++) wv[w][lane * 8 + k] = av[k];
    __syncthreads();
    {
        float hv = 0.f;
#pragma unroll
        for (int w2 = 0; w2 < 8; w2++) hv += wv[w2][t];
        g_hatt[(size_t)i * HID + t] = hv * linv_s[t >> 6];
    }
}

// ---------------- finalize: coord scale + x_out ----------------
__global__ __launch_bounds__(256) void finalize_kernel(const float* __restrict__ x_lig,
                                                       const float* __restrict__ c2w,
                                                       const float* __restrict__ c2b,
                                                       float* __restrict__ out) {
    const int lig = blockIdx.x * 8 + (threadIdx.x >> 5);
    const int lane = threadIdx.x & 31;
    const float4* t2 = (const float4*)(g_t2 + (size_t)lig * HID) + lane * 2;
    float4 a = t2[0], b = t2[1];
    const float4* cw = (const float4*)c2w + lane * 2;
    float4 ca = cw[0], cb = cw[1];
    float s = 0.f;
    s = fmaf(a.x / (1.f + __expf(-a.x)), ca.x, s);
    s = fmaf(a.y / (1.f + __expf(-a.y)), ca.y, s);
    s = fmaf(a.z / (1.f + __expf(-a.z)), ca.z, s);
    s = fmaf(a.w / (1.f + __expf(-a.w)), ca.w, s);
    s = fmaf(b.x / (1.f + __expf(-b.x)), cb.x, s);
    s = fmaf(b.y / (1.f + __expf(-b.y)), cb.y, s);
    s = fmaf(b.z / (1.f + __expf(-b.z)), cb.z, s);
    s = fmaf(b.w / (1.f + __expf(-b.w)), cb.w, s);
    s = wsum(s);
    if (lane == 0) {
        s += c2b[0];
        float4 cm = g_cm[lig];
        float* ox = out + (size_t)NLIG * HID + lig * 3;
        ox[0] = x_lig[lig * 3 + 0] + s * cm.x;
        ox[1] = x_lig[lig * 3 + 1] + s * cm.y;
        ox[2] = x_lig[lig * 3 + 2] + s * cm.z;
    }
}

// ---------------- launch ----------------
extern "C" void kernel_launch(void* const* d_in, const int* in_sizes, int n_in,
                              void* d_out, int out_size) {
    const float* h_lig = (const float*)d_in[0];
    const float* x_lig = (const float*)d_in[1];
    const float* h_atm = (const float*)d_in[2];
    const float* x_pkt = (const float*)d_in[3];
    const float* qw = (const float*)d_in[4];
    const float* qb = (const float*)d_in[5];
    const float* kw = (const float*)d_in[6];
    const float* kb = (const float*)d_in[7];
    const float* vw = (const float*)d_in[8];
    const float* vb = (const float*)d_in[9];
    const float* ow = (const float*)d_in[10];
    const float* ob = (const float*)d_in[11];
    const float* e1w = (const float*)d_in[12];
    const float* e1b = (const float*)d_in[13];
    const float* e2w = (const float*)d_in[14];
    const float* e2b = (const float*)d_in[15];
    const float* c1w = (const float*)d_in[16];
    const float* c1b = (const float*)d_in[17];
    const float* c2w = (const float*)d_in[18];
    const float* c2b = (const float*)d_in[19];
    float* out = (float*)d_out;

    __nv_bfloat16 *Abf, *hligbf, *kwbf, *vwbf, *qwbf, *Kbf, *Vbf;
    float *Qp, *hattp, *t2p;
    cudaGetSymbolAddress((void**)&Abf, g_Abf);
    cudaGetSymbolAddress((void**)&hligbf, g_hligbf);
    cudaGetSymbolAddress((void**)&kwbf, g_kwbf);
    cudaGetSymbolAddress((void**)&vwbf, g_vwbf);
    cudaGetSymbolAddress((void**)&qwbf, g_qwbf);
    cudaGetSymbolAddress((void**)&Kbf, g_Kbf);
    cudaGetSymbolAddress((void**)&Vbf, g_Vbf);
    cudaGetSymbolAddress((void**)&Qp, g_Q);
    cudaGetSymbolAddress((void**)&hattp, g_hatt);
    cudaGetSymbolAddress((void**)&t2p, g_t2);

    // launch 0: fused table + xp4 prep
    prep_misc<<<48, 256>>>(x_pkt, e1w, e1b, e2w, e2b);
    // launch 1: fused fp32->bf16 conversions
    f2bf_all<<<(SZ4 / 4 + 255) / 256, 256>>>(h_atm, h_lig, kw, vw, qw);
    // launches 2-4: tensor-core projections
    gemm_mma<true><<<dim3(NLIG / 64, HID / 64), 256>>>(hligbf, qwbf, qb, Qp, NLIG, HID, HID);
    gemm_mma<false><<<dim3(NPKT / 64, HID / 64), 256>>>(Abf, kwbf, kb, Kbf, NPKT, HID, ADIM);
    gemm_mma<false><<<dim3(NPKT / 64, HID / 64), 256>>>(Abf, vwbf, vb, Vbf, NPKT, HID, ADIM);
    // launch 5: attention (ncu -s 5 -c 1 captures this)
    attn_kernel<<<NLIG, 256>>>(x_lig);
    // launches 6-7: epilogue GEMMs
    gemm64<<<dim3(NLIG / 64, HID / 64), 256>>>(hattp, ow, ob, h_lig, out, NLIG, HID, HID);
    gemm64<<<dim3(NLIG / 64, HID / 64), 256>>>(hattp, c1w, c1b, nullptr, t2p, NLIG, HID, HID);
    // launch 8: finalize coords
    finalize_kernel<<<NLIG / 8, 256>>>(x_lig, c2w, c2b, out);
}

// round 5
// speedup vs baseline: 3.2702x; 1.1821x over previous
#include <cuda_runtime.h>
#include <cuda_bf16.h>
#include <math.h>
#include <stdint.h>

#define NLIG 1024
#define NPKT 8192
#define HID 256
#define ADIM 512
#define TABN 4096
#define CUTOFF 10.0f
#define CAP 1536

// ---------------- device scratch ----------------
__device__ __nv_bfloat16 g_Abf[NPKT * ADIM];
__device__ __nv_bfloat16 g_hligbf[NLIG * HID];
__device__ __nv_bfloat16 g_kwbf[ADIM * HID];
__device__ __nv_bfloat16 g_vwbf[ADIM * HID];
__device__ __nv_bfloat16 g_qwbf[HID * HID];
__device__ __nv_bfloat16 g_Kbf[NPKT * HID];
__device__ __nv_bfloat16 g_Vbf[NPKT * HID];
__device__ float  g_Q[NLIG * HID];
__device__ float  g_hatt[NLIG * HID];
__device__ float  g_t2[NLIG * HID];
__device__ float4 g_cm[NLIG];
__device__ float4 g_xp4[NPKT];
__device__ float4 g_tab[TABN];

// ---------------- helpers ----------------
__device__ __forceinline__ float wsum(float v) {
    v += __shfl_xor_sync(0xffffffffu, v, 16);
    v += __shfl_xor_sync(0xffffffffu, v, 8);
    v += __shfl_xor_sync(0xffffffffu, v, 4);
    v += __shfl_xor_sync(0xffffffffu, v, 2);
    v += __shfl_xor_sync(0xffffffffu, v, 1);
    return v;
}
__device__ __forceinline__ float wmax(float v) {
    v = fmaxf(v, __shfl_xor_sync(0xffffffffu, v, 16));
    v = fmaxf(v, __shfl_xor_sync(0xffffffffu, v, 8));
    v = fmaxf(v, __shfl_xor_sync(0xffffffffu, v, 4));
    v = fmaxf(v, __shfl_xor_sync(0xffffffffu, v, 2));
    v = fmaxf(v, __shfl_xor_sync(0xffffffffu, v, 1));
    return v;
}
__device__ __forceinline__ uint32_t smem_u32(const void* p) {
    return (uint32_t)__cvta_generic_to_shared(p);
}
__device__ __forceinline__ void cp_async16(uint32_t dst, const void* src) {
    asm volatile("cp.async.cg.shared.global [%0], [%1], 16;" :: "r"(dst), "l"(src));
}
__device__ __forceinline__ float dot8(const float4& qa, const float4& qb, const uint4& kr) {
    float2 k0 = __bfloat1622float2(*(const __nv_bfloat162*)&kr.x);
    float2 k1 = __bfloat1622float2(*(const __nv_bfloat162*)&kr.y);
    float2 k2 = __bfloat1622float2(*(const __nv_bfloat162*)&kr.z);
    float2 k3 = __bfloat1622float2(*(const __nv_bfloat162*)&kr.w);
    return qa.x * k0.x + qa.y * k0.y + qa.z * k1.x + qa.w * k1.y +
           qb.x * k2.x + qb.y * k2.y + qb.z * k3.x + qb.w * k3.y;
}

// ---------------- fused prep: table (blocks 0-15) + xp4 (blocks 16-47) ----
__global__ void prep_misc(const float* __restrict__ xp,
                          const float* __restrict__ e1w,
                          const float* __restrict__ e1b,
                          const float* __restrict__ e2w,
                          const float* __restrict__ e2b) {
    int b = blockIdx.x, t = threadIdx.x;
    if (b < 16) {
        int e = b * 256 + t;
        float d = (float)e * (CUTOFF / (float)(TABN - 1));
        float a0 = e2b[0], a1 = e2b[1], a2 = e2b[2], a3 = e2b[3];
        for (int u = 0; u < HID; u++) {
            float z = fmaf(d, e1w[u], e1b[u]);
            float s = z / (1.0f + expf(-z));
            a0 = fmaf(s, e2w[u * 4 + 0], a0);
            a1 = fmaf(s, e2w[u * 4 + 1], a1);
            a2 = fmaf(s, e2w[u * 4 + 2], a2);
            a3 = fmaf(s, e2w[u * 4 + 3], a3);
        }
        g_tab[e] = make_float4(a0, a1, a2, a3);
    } else {
        int j = (b - 16) * 256 + t;
        g_xp4[j] = make_float4(xp[j * 3 + 0], xp[j * 3 + 1], xp[j * 3 + 2], 0.f);
    }
}

// ---------------- fused fp32 -> bf16 ----------------
#define SZ0 (NPKT * ADIM)
#define SZ1 (SZ0 + NLIG * HID)
#define SZ2 (SZ1 + ADIM * HID)
#define SZ3 (SZ2 + ADIM * HID)
#define SZ4 (SZ3 + HID * HID)
__global__ void f2bf_all(const float* __restrict__ h_atm, const float* __restrict__ h_lig,
                         const float* __restrict__ kw, const float* __restrict__ vw,
                         const float* __restrict__ qw) {
    long i4 = (long)(blockIdx.x * 256 + threadIdx.x) * 4;
    const float* src;
    __nv_bfloat16* dst;
    long off;
    if (i4 < SZ0)      { src = h_atm; dst = g_Abf;    off = i4; }
    else if (i4 < SZ1) { src = h_lig; dst = g_hligbf; off = i4 - SZ0; }
    else if (i4 < SZ2) { src = kw;    dst = g_kwbf;   off = i4 - SZ1; }
    else if (i4 < SZ3) { src = vw;    dst = g_vwbf;   off = i4 - SZ2; }
    else if (i4 < SZ4) { src = qw;    dst = g_qwbf;   off = i4 - SZ3; }
    else return;
    float4 v = *(const float4*)(src + off);
    *(__nv_bfloat162*)(dst + off)     = __floats2bfloat162_rn(v.x, v.y);
    *(__nv_bfloat162*)(dst + off + 2) = __floats2bfloat162_rn(v.z, v.w);
}

// ---------------- bf16 tensor-core GEMM, 2-stage cp.async pipeline ----------
// BM=64, BN=64, BK=32; 8 warps in 4(m) x 2(n); warp tile 16x32.
template <bool FLOATOUT>
__global__ __launch_bounds__(256) void gemm_mma(const __nv_bfloat16* __restrict__ A,
                                                const __nv_bfloat16* __restrict__ W,
                                                const float* __restrict__ bias,
                                                void* __restrict__ Cv,
                                                int M, int N, int K) {
    __shared__ __nv_bfloat16 As[2][64][40];
    __shared__ __nv_bfloat16 Bs[2][32][72];
    const int t = threadIdx.x;
    const int warp = t >> 5, lane = t & 31;
    const int wm = warp >> 1, wn = warp & 1;
    const int bm = blockIdx.x * 64, bn = blockIdx.y * 64;
    const int ar = t >> 2, ac = (t & 3) * 8;
    const int br = t >> 3, bc = (t & 7) * 8;

    float acc[4][4];
#pragma unroll
    for (int nt = 0; nt < 4; nt++)
#pragma unroll
        for (int r = 0; r < 4; r++) acc[nt][r] = 0.f;

    const int NK = K / 32;
    // prologue: stage 0
    cp_async16(smem_u32(&As[0][ar][ac]), A + (size_t)(bm + ar) * K + ac);
    cp_async16(smem_u32(&Bs[0][br][bc]), W + (size_t)br * N + bn + bc);
    asm volatile("cp.async.commit_group;");

    for (int kt = 0; kt < NK; kt++) {
        if (kt + 1 < NK) {
            int s = (kt + 1) & 1, ko = (kt + 1) * 32;
            cp_async16(smem_u32(&As[s][ar][ac]), A + (size_t)(bm + ar) * K + ko + ac);
            cp_async16(smem_u32(&Bs[s][br][bc]), W + (size_t)(ko + br) * N + bn + bc);
            asm volatile("cp.async.commit_group;");
            asm volatile("cp.async.wait_group 1;");
        } else {
            asm volatile("cp.async.wait_group 0;");
        }
        __syncthreads();
        const int st = kt & 1;
#pragma unroll
        for (int kk = 0; kk < 32; kk += 16) {
            uint32_t a[4];
            {
                int row = wm * 16 + (lane & 15);
                int col = kk + 8 * (lane >> 4);
                uint32_t addr = smem_u32(&As[st][row][col]);
                asm volatile("ldmatrix.sync.aligned.m8n8.x4.shared.b16 {%0,%1,%2,%3}, [%4];"
                             : "=r"(a[0]), "=r"(a[1]), "=r"(a[2]), "=r"(a[3])
                             : "r"(addr));
            }
            uint32_t b[4][2];
#pragma unroll
            for (int nt2 = 0; nt2 < 2; nt2++) {
                int row = kk + (lane & 15);
                int col = wn * 32 + nt2 * 16 + 8 * (lane >> 4);
                uint32_t addr = smem_u32(&Bs[st][row][col]);
                uint32_t b0, b1, b2, b3;
                asm volatile("ldmatrix.sync.aligned.m8n8.x4.trans.shared.b16 {%0,%1,%2,%3}, [%4];"
                             : "=r"(b0), "=r"(b1), "=r"(b2), "=r"(b3)
                             : "r"(addr));
                b[nt2 * 2 + 0][0] = b0; b[nt2 * 2 + 0][1] = b1;
                b[nt2 * 2 + 1][0] = b2; b[nt2 * 2 + 1][1] = b3;
            }
#pragma unroll
            for (int nt = 0; nt < 4; nt++) {
                asm volatile(
                    "mma.sync.aligned.m16n8k16.row.col.f32.bf16.bf16.f32 "
                    "{%0,%1,%2,%3}, {%4,%5,%6,%7}, {%8,%9}, {%0,%1,%2,%3};"
                    : "+f"(acc[nt][0]), "+f"(acc[nt][1]), "+f"(acc[nt][2]), "+f"(acc[nt][3])
                    : "r"(a[0]), "r"(a[1]), "r"(a[2]), "r"(a[3]),
                      "r"(b[nt][0]), "r"(b[nt][1]));
            }
        }
        __syncthreads();
    }

#pragma unroll
    for (int nt = 0; nt < 4; nt++) {
        int row0 = bm + wm * 16 + (lane >> 2);
        int col = bn + wn * 32 + nt * 8 + (lane & 3) * 2;
        float bi0 = bias[col], bi1 = bias[col + 1];
        float v0 = acc[nt][0] + bi0, v1 = acc[nt][1] + bi1;
        float v2 = acc[nt][2] + bi0, v3 = acc[nt][3] + bi1;
        if (FLOATOUT) {
            float* C = (float*)Cv;
            *(float2*)(C + (size_t)row0 * N + col) = make_float2(v0, v1);
            *(float2*)(C + (size_t)(row0 + 8) * N + col) = make_float2(v2, v3);
        } else {
            __nv_bfloat16* C = (__nv_bfloat16*)Cv;
            *(__nv_bfloat162*)(C + (size_t)row0 * N + col) = __floats2bfloat162_rn(v0, v1);
            *(__nv_bfloat162*)(C + (size_t)(row0 + 8) * N + col) = __floats2bfloat162_rn(v2, v3);
        }
    }
}

// ---------------- merged epilogue GEMM (z=0: ow->out+residual, z=1: c1w->t2) ----
__global__ __launch_bounds__(256) void gemm64_epi(const float* __restrict__ A,
                                                  const float* __restrict__ ow,
                                                  const float* __restrict__ ob,
                                                  const float* __restrict__ c1w,
                                                  const float* __restrict__ c1b,
                                                  const float* __restrict__ h_lig,
                                                  float* __restrict__ out,
                                                  float* __restrict__ t2) {
    const float* W   = blockIdx.z ? c1w : ow;
    const float* bias = blockIdx.z ? c1b : ob;
    const float* R   = blockIdx.z ? nullptr : h_lig;
    float* C         = blockIdx.z ? t2 : out;
    const int N = HID, Kd = HID;

    __shared__ float As[64][16];
    __shared__ float Bs[16][64];
    const int t = threadIdx.x;
    const int tx = t & 15, ty = t >> 4;
    const int bm = blockIdx.x * 64, bn = blockIdx.y * 64;
    const int arow = t >> 2, ac4 = (t & 3) * 4;
    const int brow = t >> 4, bc4 = (t & 15) * 4;

    float acc[4][4];
#pragma unroll
    for (int i = 0; i < 4; i++)
#pragma unroll
        for (int j = 0; j < 4; j++) acc[i][j] = 0.f;

    for (int kt = 0; kt < Kd; kt += 16) {
        float4 av = *(const float4*)(A + (size_t)(bm + arow) * Kd + kt + ac4);
        float4 bv = *(const float4*)(W + (size_t)(kt + brow) * N + bn + bc4);
        *(float4*)&As[arow][ac4] = av;
        *(float4*)&Bs[brow][bc4] = bv;
        __syncthreads();
#pragma unroll
        for (int k = 0; k < 16; k++) {
            float4 bq = *(const float4*)&Bs[k][tx * 4];
            float a0 = As[ty * 4 + 0][k];
            float a1 = As[ty * 4 + 1][k];
            float a2 = As[ty * 4 + 2][k];
            float a3 = As[ty * 4 + 3][k];
            acc[0][0] = fmaf(a0, bq.x, acc[0][0]); acc[0][1] = fmaf(a0, bq.y, acc[0][1]);
            acc[0][2] = fmaf(a0, bq.z, acc[0][2]); acc[0][3] = fmaf(a0, bq.w, acc[0][3]);
            acc[1][0] = fmaf(a1, bq.x, acc[1][0]); acc[1][1] = fmaf(a1, bq.y, acc[1][1]);
            acc[1][2] = fmaf(a1, bq.z, acc[1][2]); acc[1][3] = fmaf(a1, bq.w, acc[1][3]);
            acc[2][0] = fmaf(a2, bq.x, acc[2][0]); acc[2][1] = fmaf(a2, bq.y, acc[2][1]);
            acc[2][2] = fmaf(a2, bq.z, acc[2][2]); acc[2][3] = fmaf(a2, bq.w, acc[2][3]);
            acc[3][0] = fmaf(a3, bq.x, acc[3][0]); acc[3][1] = fmaf(a3, bq.y, acc[3][1]);
            acc[3][2] = fmaf(a3, bq.z, acc[3][2]); acc[3][3] = fmaf(a3, bq.w, acc[3][3]);
        }
        __syncthreads();
    }

#pragma unroll
    for (int i = 0; i < 4; i++) {
        int row = bm + ty * 4 + i;
        int col = bn + tx * 4;
        float v0 = acc[i][0] + bias[col + 0];
        float v1 = acc[i][1] + bias[col + 1];
        float v2 = acc[i][2] + bias[col + 2];
        float v3 = acc[i][3] + bias[col + 3];
        if (R) {
            float4 r = *(const float4*)(R + (size_t)row * N + col);
            v0 += r.x; v1 += r.y; v2 += r.z; v3 += r.w;
        }
        *(float4*)(C + (size_t)row * N + col) = make_float4(v0, v1, v2, v3);
    }
}

// ---------------- attention kernel: one block per ligand ----------------
__global__ __launch_bounds__(256, 4) void attn_kernel(const float* __restrict__ x_lig) {
    const int i = blockIdx.x;
    const int t = threadIdx.x;
    const int w = t >> 5, lane = t & 31;
    const int h = lane >> 3;

    __shared__ float q_s[HID];
    __shared__ unsigned short list[CAP];
    __shared__ float4 sarr[CAP];
    __shared__ float wv[8][HID];
    __shared__ float wred[8][4];
    __shared__ float wc[8][4];
    __shared__ float m_s[4], linv_s[4];
    __shared__ float c12[12];
    __shared__ int woff[8];
    __shared__ int s_cnt;
    __shared__ float s_xl[3];

    if (t < 3) s_xl[t] = x_lig[i * 3 + t];
    q_s[t] = g_Q[(size_t)i * HID + t] * 0.125f;
    __syncthreads();
    const float xlx = s_xl[0], xly = s_xl[1], xlz = s_xl[2];

    // ---- Phase A: deterministic compaction ----
    unsigned msk = 0;
    const int jbase = t * 32;
#pragma unroll 4
    for (int k = 0; k < 32; k++) {
        float4 xp = g_xp4[jbase + k];
        float rx = xp.x - xlx, ry = xp.y - xly, rz = xp.z - xlz;
        float d2 = rx * rx + ry * ry + rz * rz;
        if (d2 < CUTOFF * CUTOFF) msk |= (1u << k);
    }
    int mycnt = __popc(msk);
    int inc = mycnt;
#pragma unroll
    for (int off = 1; off < 32; off <<= 1) {
        int v = __shfl_up_sync(0xffffffffu, inc, off);
        if (lane >= off) inc += v;
    }
    if (lane == 31) woff[w] = inc;
    __syncthreads();
    if (t == 0) {
        int run = 0;
#pragma unroll
        for (int ww = 0; ww < 8; ww++) { int v = woff[ww]; woff[ww] = run; run += v; }
        s_cnt = run;
    }
    __syncthreads();
    int offset = woff[w] + (inc - mycnt);
    unsigned mm = msk;
    while (mm) {
        int k = __ffs(mm) - 1;
        mm &= mm - 1;
        if (offset < CAP) list[offset] = (unsigned short)(jbase + k);
        offset++;
    }
    __syncthreads();
    const int nact = (s_cnt < CAP) ? s_cnt : CAP;

    // ---- B1: warp-per-pair Q.K dots, 4-way unrolled gather ----
    {
        const float4 qa = ((const float4*)q_s)[lane * 2];
        const float4 qb = ((const float4*)q_s)[lane * 2 + 1];
        float* sf = (float*)sarr;
        int p = w;
        for (; p + 24 < nact; p += 32) {
            int j0 = list[p], j1 = list[p + 8], j2 = list[p + 16], j3 = list[p + 24];
            uint4 k0 = *(const uint4*)(g_Kbf + (size_t)j0 * HID + lane * 8);
            uint4 k1 = *(const uint4*)(g_Kbf + (size_t)j1 * HID + lane * 8);
            uint4 k2 = *(const uint4*)(g_Kbf + (size_t)j2 * HID + lane * 8);
            uint4 k3 = *(const uint4*)(g_Kbf + (size_t)j3 * HID + lane * 8);
            float d0 = dot8(qa, qb, k0);
            float d1 = dot8(qa, qb, k1);
            float d2 = dot8(qa, qb, k2);
            float d3 = dot8(qa, qb, k3);
            d0 += __shfl_xor_sync(0xffffffffu, d0, 1);
            d1 += __shfl_xor_sync(0xffffffffu, d1, 1);
            d2 += __shfl_xor_sync(0xffffffffu, d2, 1);
            d3 += __shfl_xor_sync(0xffffffffu, d3, 1);
            d0 += __shfl_xor_sync(0xffffffffu, d0, 2);
            d1 += __shfl_xor_sync(0xffffffffu, d1, 2);
            d2 += __shfl_xor_sync(0xffffffffu, d2, 2);
            d3 += __shfl_xor_sync(0xffffffffu, d3, 2);
            d0 += __shfl_xor_sync(0xffffffffu, d0, 4);
            d1 += __shfl_xor_sync(0xffffffffu, d1, 4);
            d2 += __shfl_xor_sync(0xffffffffu, d2, 4);
            d3 += __shfl_xor_sync(0xffffffffu, d3, 4);
            if ((lane & 7) == 0) {
                int hh = lane >> 3;
                sf[p * 4 + hh] = d0;
                sf[(p + 8) * 4 + hh] = d1;
                sf[(p + 16) * 4 + hh] = d2;
                sf[(p + 24) * 4 + hh] = d3;
            }
        }
        for (; p < nact; p += 8) {
            int jj = list[p];
            uint4 kr = *(const uint4*)(g_Kbf + (size_t)jj * HID + lane * 8);
            float dp = dot8(qa, qb, kr);
            dp += __shfl_xor_sync(0xffffffffu, dp, 1);
            dp += __shfl_xor_sync(0xffffffffu, dp, 2);
            dp += __shfl_xor_sync(0xffffffffu, dp, 4);
            if ((lane & 7) == 0) sf[p * 4 + (lane >> 3)] = dp;
        }
    }
    __syncthreads();

    // ---- B2a pass 1: thread-per-pair edge bias + block max ----
    float mx0 = -INFINITY, mx1 = -INFINITY, mx2 = -INFINITY, mx3 = -INFINITY;
    for (int p = t; p < nact; p += 256) {
        float4 s = sarr[p];
        const int jj = list[p];
        float4 xp = g_xp4[jj];
        float rx = xp.x - xlx, ry = xp.y - xly, rz = xp.z - xlz;
        float d = sqrtf(rx * rx + ry * ry + rz * rz);
        float tp = d * ((float)(TABN - 1) / CUTOFF);
        int k0 = (int)tp;
        k0 = (k0 > TABN - 2) ? (TABN - 2) : k0;
        float fr = tp - (float)k0;
        float4 f0 = g_tab[k0], f1 = g_tab[k0 + 1];
        s.x += f0.x + fr * (f1.x - f0.x);
        s.y += f0.y + fr * (f1.y - f0.y);
        s.z += f0.z + fr * (f1.z - f0.z);
        s.w += f0.w + fr * (f1.w - f0.w);
        sarr[p] = s;
        mx0 = fmaxf(mx0, s.x); mx1 = fmaxf(mx1, s.y);
        mx2 = fmaxf(mx2, s.z); mx3 = fmaxf(mx3, s.w);
    }
    mx0 = wmax(mx0); mx1 = wmax(mx1); mx2 = wmax(mx2); mx3 = wmax(mx3);
    if (lane == 0) { wred[w][0] = mx0; wred[w][1] = mx1; wred[w][2] = mx2; wred[w][3] = mx3; }
    __syncthreads();
    if (t < 4) {
        float m = -INFINITY;
#pragma unroll
        for (int w2 = 0; w2 < 8; w2++) m = fmaxf(m, wred[w2][t]);
        m_s[t] = m;
    }
    __syncthreads();

    // ---- B2a pass 2: warp-per-head exp + l-sums + coord sums ----
    {
        const int hh = w & 3;
        const int half = w >> 2;
        const float mh = m_s[hh];
        float* sf = (float*)sarr;
        float l = 0.f, cx = 0.f, cy = 0.f, cz = 0.f;
        for (int p = half * 32 + lane; p < nact; p += 64) {
            float s = sf[p * 4 + hh];
            float pe = __expf(s - mh);
            sf[p * 4 + hh] = pe;
            l += pe;
            const int jj = list[p];
            float4 xp = g_xp4[jj];
            float rx = xp.x - xlx, ry = xp.y - xly, rz = xp.z - xlz;
            float d2 = rx * rx + ry * ry + rz * rz;
            float invd = rsqrtf(d2 + 1e-16f);
            float pin = pe * invd;
            cx = fmaf(pin, rx, cx); cy = fmaf(pin, ry, cy); cz = fmaf(pin, rz, cz);
        }
        l = wsum(l); cx = wsum(cx); cy = wsum(cy); cz = wsum(cz);
        if (lane == 0) {
            wred[w][0] = l;
            wc[w][0] = cx; wc[w][1] = cy; wc[w][2] = cz;
        }
    }
    __syncthreads();
    if (t < 4) {
        float L = wred[t][0] + wred[t + 4][0];
        linv_s[t] = (L > 0.f) ? __fdividef(1.0f, L) : 0.f;
    }
    if (t >= 32 && t < 44) {
        int j = t - 32;
        int h2 = j / 3, ax = j % 3;
        c12[j] = wc[h2][ax] + wc[h2 + 4][ax];
    }
    __syncthreads();
    if (t < 3) {
        float v = 0.f;
#pragma unroll
        for (int h2 = 0; h2 < 4; h2++) v += c12[h2 * 3 + t] * linv_s[h2];
        ((float*)&g_cm[i])[t] = 0.25f * v;
    }

    // ---- B2b: warp-per-pair weighted V accumulation, 4-way unrolled ----
    float av[8];
#pragma unroll
    for (int k = 0; k < 8; k++) av[k] = 0.f;
    {
        const float* pef = (const float*)sarr;
        int p = w;
        for (; p + 24 < nact; p += 32) {
            int j0 = list[p], j1 = list[p + 8], j2 = list[p + 16], j3 = list[p + 24];
            float pe0 = pef[p * 4 + h];
            float pe1 = pef[(p + 8) * 4 + h];
            float pe2 = pef[(p + 16) * 4 + h];
            float pe3 = pef[(p + 24) * 4 + h];
            uint4 r0 = *(const uint4*)(g_Vbf + (size_t)j0 * HID + lane * 8);
            uint4 r1 = *(const uint4*)(g_Vbf + (size_t)j1 * HID + lane * 8);
            uint4 r2 = *(const uint4*)(g_Vbf + (size_t)j2 * HID + lane * 8);
            uint4 r3 = *(const uint4*)(g_Vbf + (size_t)j3 * HID + lane * 8);
#pragma unroll
            for (int q4 = 0; q4 < 4; q4++) {
                uint4 rr = q4 == 0 ? r0 : (q4 == 1 ? r1 : (q4 == 2 ? r2 : r3));
                float pe = q4 == 0 ? pe0 : (q4 == 1 ? pe1 : (q4 == 2 ? pe2 : pe3));
                float2 v0 = __bfloat1622float2(*(const __nv_bfloat162*)&rr.x);
                float2 v1 = __bfloat1622float2(*(const __nv_bfloat162*)&rr.y);
                float2 v2 = __bfloat1622float2(*(const __nv_bfloat162*)&rr.z);
                float2 v3 = __bfloat1622float2(*(const __nv_bfloat162*)&rr.w);
                av[0] = fmaf(pe, v0.x, av[0]); av[1] = fmaf(pe, v0.y, av[1]);
                av[2] = fmaf(pe, v1.x, av[2]); av[3] = fmaf(pe, v1.y, av[3]);
                av[4] = fmaf(pe, v2.x, av[4]); av[5] = fmaf(pe, v2.y, av[5]);
                av[6] = fmaf(pe, v3.x, av[6]); av[7] = fmaf(pe, v3.y, av[7]);
            }
        }
        for (; p < nact; p += 8) {
            int jj = list[p];
            float pe = pef[p * 4 + h];
            uint4 vr = *(const uint4*)(g_Vbf + (size_t)jj * HID + lane * 8);
            float2 v0 = __bfloat1622float2(*(const __nv_bfloat162*)&vr.x);
            float2 v1 = __bfloat1622float2(*(const __nv_bfloat162*)&vr.y);
            float2 v2 = __bfloat1622float2(*(const __nv_bfloat162*)&vr.z);
            float2 v3 = __bfloat1622float2(*(const __nv_bfloat162*)&vr.w);
            av[0] = fmaf(pe, v0.x, av[0]); av[1] = fmaf(pe, v0.y, av[1]);
            av[2] = fmaf(pe, v1.x, av[2]); av[3] = fmaf(pe, v1.y, av[3]);
            av[4] = fmaf(pe, v2.x, av[4]); av[5] = fmaf(pe, v2.y, av[5]);
            av[6] = fmaf(pe, v3.x, av[6]); av[7] = fmaf(pe, v3.y, av[7]);
        }
    }
#pragma unroll
    for (int k = 0; k < 8; k++) wv[w][lane * 8 + k] = av[k];
    __syncthreads();
    {
        float hv = 0.f;
#pragma unroll
        for (int w2 = 0; w2 < 8; w2++) hv += wv[w2][t];
        g_hatt[(size_t)i * HID + t] = hv * linv_s[t >> 6];
    }
}

// ---------------- finalize: coord scale + x_out ----------------
__global__ __launch_bounds__(256) void finalize_kernel(const float* __restrict__ x_lig,
                                                       const float* __restrict__ c2w,
                                                       const float* __restrict__ c2b,
                                                       float* __restrict__ out) {
    const int lig = blockIdx.x * 8 + (threadIdx.x >> 5);
    const int lane = threadIdx.x & 31;
    const float4* t2 = (const float4*)(g_t2 + (size_t)lig * HID) + lane * 2;
    float4 a = t2[0], b = t2[1];
    const float4* cw = (const float4*)c2w + lane * 2;
    float4 ca = cw[0], cb = cw[1];
    float s = 0.f;
    s = fmaf(a.x / (1.f + __expf(-a.x)), ca.x, s);
    s = fmaf(a.y / (1.f + __expf(-a.y)), ca.y, s);
    s = fmaf(a.z / (1.f + __expf(-a.z)), ca.z, s);
    s = fmaf(a.w / (1.f + __expf(-a.w)), ca.w, s);
    s = fmaf(b.x / (1.f + __expf(-b.x)), cb.x, s);
    s = fmaf(b.y / (1.f + __expf(-b.y)), cb.y, s);
    s = fmaf(b.z / (1.f + __expf(-b.z)), cb.z, s);
    s = fmaf(b.w / (1.f + __expf(-b.w)), cb.w, s);
    s = wsum(s);
    if (lane == 0) {
        s += c2b[0];
        float4 cm = g_cm[lig];
        float* ox = out + (size_t)NLIG * HID + lig * 3;
        ox[0] = x_lig[lig * 3 + 0] + s * cm.x;
        ox[1] = x_lig[lig * 3 + 1] + s * cm.y;
        ox[2] = x_lig[lig * 3 + 2] + s * cm.z;
    }
}

// ---------------- launch ----------------
extern "C" void kernel_launch(void* const* d_in, const int* in_sizes, int n_in,
                              void* d_out, int out_size) {
    const float* h_lig = (const float*)d_in[0];
    const float* x_lig = (const float*)d_in[1];
    const float* h_atm = (const float*)d_in[2];
    const float* x_pkt = (const float*)d_in[3];
    const float* qw = (const float*)d_in[4];
    const float* qb = (const float*)d_in[5];
    const float* kw = (const float*)d_in[6];
    const float* kb = (const float*)d_in[7];
    const float* vw = (const float*)d_in[8];
    const float* vb = (const float*)d_in[9];
    const float* ow = (const float*)d_in[10];
    const float* ob = (const float*)d_in[11];
    const float* e1w = (const float*)d_in[12];
    const float* e1b = (const float*)d_in[13];
    const float* e2w = (const float*)d_in[14];
    const float* e2b = (const float*)d_in[15];
    const float* c1w = (const float*)d_in[16];
    const float* c1b = (const float*)d_in[17];
    const float* c2w = (const float*)d_in[18];
    const float* c2b = (const float*)d_in[19];
    float* out = (float*)d_out;

    __nv_bfloat16 *Abf, *hligbf, *kwbf, *vwbf, *qwbf, *Kbf, *Vbf;
    float *Qp, *hattp, *t2p;
    cudaGetSymbolAddress((void**)&Abf, g_Abf);
    cudaGetSymbolAddress((void**)&hligbf, g_hligbf);
    cudaGetSymbolAddress((void**)&kwbf, g_kwbf);
    cudaGetSymbolAddress((void**)&vwbf, g_vwbf);
    cudaGetSymbolAddress((void**)&qwbf, g_qwbf);
    cudaGetSymbolAddress((void**)&Kbf, g_Kbf);
    cudaGetSymbolAddress((void**)&Vbf, g_Vbf);
    cudaGetSymbolAddress((void**)&Qp, g_Q);
    cudaGetSymbolAddress((void**)&hattp, g_hatt);
    cudaGetSymbolAddress((void**)&t2p, g_t2);

    prep_misc<<<48, 256>>>(x_pkt, e1w, e1b, e2w, e2b);                                   // 0
    f2bf_all<<<(SZ4 / 4 + 255) / 256, 256>>>(h_atm, h_lig, kw, vw, qw);                  // 1
    gemm_mma<true><<<dim3(NLIG / 64, HID / 64), 256>>>(hligbf, qwbf, qb, Qp, NLIG, HID, HID);   // 2
    gemm_mma<false><<<dim3(NPKT / 64, HID / 64), 256>>>(Abf, kwbf, kb, Kbf, NPKT, HID, ADIM);   // 3
    gemm_mma<false><<<dim3(NPKT / 64, HID / 64), 256>>>(Abf, vwbf, vb, Vbf, NPKT, HID, ADIM);   // 4
    attn_kernel<<<NLIG, 256>>>(x_lig);                                                   // 5 (ncu)
    gemm64_epi<<<dim3(NLIG / 64, HID / 64, 2), 256>>>(hattp, ow, ob, c1w, c1b, h_lig, out, t2p); // 6
    finalize_kernel<<<NLIG / 8, 256>>>(x_lig, c2w, c2b, out);                            // 7
}